// round 7
// baseline (speedup 1.0000x reference)
#include <cuda_runtime.h>
#include <cuda_bf16.h>
#include <cuda_pipeline.h>
#include <mma.h>
#include <math.h>

using namespace nvcuda;

constexpr int kEmbed   = 1024;
constexpr int kHeads   = 16;
constexpr int kHeadDim = 64;
constexpr int kSeq     = 2048;
constexpr int kBatch   = 4;
constexpr int kQkvN    = 3 * kEmbed;          // 3072
constexpr int kRows    = kBatch * kSeq;       // 8192
constexpr int kBHT     = kBatch * kHeads * kSeq * kHeadDim;

// -------- scratch (static device globals; no runtime allocation) --------
__device__ __align__(128) __nv_bfloat16 g_xh[kRows * kEmbed];
__device__ __align__(128) __nv_bfloat16 g_xl[kRows * kEmbed];
__device__ __align__(128) __nv_bfloat16 g_wqkvh[kEmbed * kQkvN];
__device__ __align__(128) __nv_bfloat16 g_wqkvl[kEmbed * kQkvN];
__device__ __align__(128) float g_bqkv[kQkvN];
__device__ __align__(128) __nv_bfloat16 g_qh2[kBHT];
__device__ __align__(128) __nv_bfloat16 g_ql2[kBHT];
__device__ __align__(128) __nv_bfloat16 g_kh2[kBHT];
__device__ __align__(128) __nv_bfloat16 g_kl2[kBHT];
__device__ __align__(128) __nv_bfloat16 g_vh2[kBHT];
__device__ __align__(128) __nv_bfloat16 g_vl2[kBHT];
__device__ __align__(128) __nv_bfloat16 g_atth[kRows * kEmbed];
__device__ __align__(128) __nv_bfloat16 g_attl[kRows * kEmbed];
__device__ __align__(128) __nv_bfloat16 g_wph[kEmbed * kEmbed];
__device__ __align__(128) __nv_bfloat16 g_wpl[kEmbed * kEmbed];

// ======================= conversion / packing =======================
__device__ __forceinline__ void bf16_split(float v, __nv_bfloat16& hi, __nv_bfloat16& lo) {
    hi = __float2bfloat16(v);
    lo = __float2bfloat16(v - __bfloat162float(hi));
}

__global__ void convert_x_kernel(const float* __restrict__ x) {
    int idx = blockIdx.x * blockDim.x + threadIdx.x;
    if (idx < kRows * kEmbed) {
        __nv_bfloat16 h, l;
        bf16_split(x[idx], h, l);
        g_xh[idx] = h; g_xl[idx] = l;
    }
}

__global__ void pack_qkv_kernel(const float* __restrict__ Wq, const float* __restrict__ Wk,
                                const float* __restrict__ Wv, const float* __restrict__ bq,
                                const float* __restrict__ bk, const float* __restrict__ bv) {
    int idx = blockIdx.x * blockDim.x + threadIdx.x;
    if (idx < kEmbed * kQkvN) {
        int e = idx / kQkvN;
        int n = idx % kQkvN;
        int which = n >> 10;
        int hd    = n & 1023;
        int h = hd >> 6, d = hd & 63;
        const float* W = (which == 0) ? Wq : (which == 1) ? Wk : Wv;
        float v = W[((size_t)h * kEmbed + e) * kHeadDim + d];
        __nv_bfloat16 hi, lo;
        bf16_split(v, hi, lo);
        g_wqkvh[idx] = hi; g_wqkvl[idx] = lo;
    }
    if (idx < kQkvN) {
        int which = idx >> 10;
        int hd    = idx & 1023;
        const float* bb = (which == 0) ? bq : (which == 1) ? bk : bv;
        g_bqkv[idx] = bb[hd];
    }
}

__global__ void pack_wp_kernel(const float* __restrict__ Wp) {
    int idx = blockIdx.x * blockDim.x + threadIdx.x;
    if (idx < kEmbed * kEmbed) {
        __nv_bfloat16 hi, lo;
        bf16_split(Wp[idx], hi, lo);
        g_wph[idx] = hi; g_wpl[idx] = lo;
    }
}

// ======================= bf16-split WMMA GEMM =======================
// acc += Ah*Bh + Ah*Bl + Al*Bh   (Al*Bl ~2^-18 relative, dropped)
// Block tile 128x128, BK=32, cp.async 3-stage, 512 threads / 16 warps,
// warp tile 32x32 (4x4 warp grid) -> low regs, 4 warps/SMSP for latency hiding.
constexpr int kGAh = 0;                      // [128][40] bf16
constexpr int kGAl = 10240;
constexpr int kGBh = 20480;                  // [32][136] bf16
constexpr int kGBl = 29184;
constexpr int kGStage = 37888;
constexpr int kGemmSmem = 3 * kGStage;       // 113664

__global__ __launch_bounds__(512, 1)
void gemm_wmma_kernel(const float* __restrict__ bias_arg, float* __restrict__ outp, int mode) {
    extern __shared__ char sm[];

    const int N = (mode == 0) ? kQkvN : kEmbed;
    const __nv_bfloat16* Ah = (mode == 0) ? g_xh : g_atth;
    const __nv_bfloat16* Al = (mode == 0) ? g_xl : g_attl;
    const __nv_bfloat16* Bh = (mode == 0) ? g_wqkvh : g_wph;
    const __nv_bfloat16* Bl = (mode == 0) ? g_wqkvl : g_wpl;
    const float* bias = (mode == 0) ? g_bqkv : bias_arg;

    const int tid  = threadIdx.x;
    const int warp = tid >> 5, lane = tid & 31;
    const int wm   = warp >> 2, wn = warp & 3;   // 4x4 warp grid
    const int bm   = blockIdx.y * 128;
    const int bn   = blockIdx.x * 128;

    const int ar = tid >> 2,  ac = (tid & 3) * 8;    // A: 128 rows x 32 cols
    const int br = tid >> 4,  bc = (tid & 15) * 8;   // B: 32 rows x 128 cols

    auto loadStage = [&](int kt, int s) {
        const int k0 = kt * 32;
        char* st = sm + s * kGStage;
        __nv_bfloat16* sAh = (__nv_bfloat16*)(st + kGAh);
        __nv_bfloat16* sAl = (__nv_bfloat16*)(st + kGAl);
        __nv_bfloat16* sBh = (__nv_bfloat16*)(st + kGBh);
        __nv_bfloat16* sBl = (__nv_bfloat16*)(st + kGBl);
        const size_t asrc = (size_t)(bm + ar) * kEmbed + k0 + ac;
        __pipeline_memcpy_async(sAh + ar * 40 + ac, Ah + asrc, 16);
        __pipeline_memcpy_async(sAl + ar * 40 + ac, Al + asrc, 16);
        const size_t bsrc = (size_t)(k0 + br) * N + bn + bc;
        __pipeline_memcpy_async(sBh + br * 136 + bc, Bh + bsrc, 16);
        __pipeline_memcpy_async(sBl + br * 136 + bc, Bl + bsrc, 16);
        __pipeline_commit();
    };

    wmma::fragment<wmma::accumulator, 16, 16, 16, float> acc[2][2];
#pragma unroll
    for (int mi = 0; mi < 2; mi++)
#pragma unroll
        for (int ni = 0; ni < 2; ni++) wmma::fill_fragment(acc[mi][ni], 0.0f);

    constexpr int NT = kEmbed / 32;   // 32 stages
    loadStage(0, 0);
    loadStage(1, 1);

    for (int kt = 0; kt < NT; kt++) {
        if (kt < NT - 2) __pipeline_wait_prior(1);
        else             __pipeline_wait_prior(0);
        __syncthreads();
        if (kt + 2 < NT) loadStage(kt + 2, (kt + 2) % 3);

        char* st = sm + (kt % 3) * kGStage;
        const __nv_bfloat16* sAh = (const __nv_bfloat16*)(st + kGAh);
        const __nv_bfloat16* sAl = (const __nv_bfloat16*)(st + kGAl);
        const __nv_bfloat16* sBh = (const __nv_bfloat16*)(st + kGBh);
        const __nv_bfloat16* sBl = (const __nv_bfloat16*)(st + kGBl);

#pragma unroll
        for (int kk = 0; kk < 2; kk++) {
            wmma::fragment<wmma::matrix_a, 16, 16, 16, __nv_bfloat16, wmma::row_major> fa[2], fal[2];
            wmma::fragment<wmma::matrix_b, 16, 16, 16, __nv_bfloat16, wmma::row_major> fb[2], fbl[2];
#pragma unroll
            for (int mi = 0; mi < 2; mi++) {
                wmma::load_matrix_sync(fa[mi],  sAh + (wm * 32 + mi * 16) * 40 + kk * 16, 40);
                wmma::load_matrix_sync(fal[mi], sAl + (wm * 32 + mi * 16) * 40 + kk * 16, 40);
            }
#pragma unroll
            for (int ni = 0; ni < 2; ni++) {
                wmma::load_matrix_sync(fb[ni],  sBh + (kk * 16) * 136 + wn * 32 + ni * 16, 136);
                wmma::load_matrix_sync(fbl[ni], sBl + (kk * 16) * 136 + wn * 32 + ni * 16, 136);
            }
#pragma unroll
            for (int mi = 0; mi < 2; mi++)
#pragma unroll
                for (int ni = 0; ni < 2; ni++) {
                    wmma::mma_sync(acc[mi][ni], fa[mi],  fb[ni],  acc[mi][ni]);
                    wmma::mma_sync(acc[mi][ni], fa[mi],  fbl[ni], acc[mi][ni]);
                    wmma::mma_sync(acc[mi][ni], fal[mi], fb[ni],  acc[mi][ni]);
                }
        }
    }

    __syncthreads();
    float* scratch = (float*)sm + warp * 320;
#pragma unroll
    for (int mi = 0; mi < 2; mi++) {
#pragma unroll
        for (int ni = 0; ni < 2; ni++) {
            wmma::store_matrix_sync(scratch, acc[mi][ni], 20, wmma::mem_row_major);
            __syncwarp();
            const int r0 = bm + wm * 32 + mi * 16;
            const int c0 = bn + wn * 32 + ni * 16;
#pragma unroll
            for (int e = 0; e < 8; e++) {
                const int idx = e * 32 + lane;
                const int rr = idx >> 4, cc = idx & 15;
                const int row = r0 + rr, col = c0 + cc;
                const float v = scratch[rr * 20 + cc] + bias[col];
                if (mode == 0) {
                    const int which = col >> 10, hd = col & 1023;
                    const int h = hd >> 6, d = hd & 63;
                    const int b = row >> 11, t = row & 2047;
                    __nv_bfloat16* dh = (which == 0) ? g_qh2 : ((which == 1) ? g_kh2 : g_vh2);
                    __nv_bfloat16* dl = (which == 0) ? g_ql2 : ((which == 1) ? g_kl2 : g_vl2);
                    const size_t o = (((size_t)(b * kHeads + h) * kSeq) + t) * kHeadDim + d;
                    __nv_bfloat16 hi, lo;
                    bf16_split(v, hi, lo);
                    dh[o] = hi; dl[o] = lo;
                } else {
                    outp[(size_t)row * kEmbed + col] = v;
                }
            }
            __syncwarp();
        }
    }
}

// ======================= WMMA causal attention =======================
// 256 threads, 128 q-rows/CTA (warp owns 16), kv tile 64, cp.async double buffer.
// Unnormalized exp (|score| <~ 3) -> no online rescaling; O lives in fragments.
constexpr int kKVBuf  = 4 * 9216;            // kh,kl,vh,vl each bf16[64][72]
constexpr int kAPH    = 2 * kKVBuf;          // 73728, bf16[128][72]
constexpr int kAPL    = kAPH + 18432;        // 92160
constexpr int kASS    = kAPL + 18432;        // 110592, float[128][68]
constexpr int kAttnSmem = kASS + 34816;      // 145408

__global__ __launch_bounds__(256, 1)
void attn_wmma_kernel() {
    extern __shared__ char sm[];
    __nv_bfloat16* ph = (__nv_bfloat16*)(sm + kAPH);
    __nv_bfloat16* pl = (__nv_bfloat16*)(sm + kAPL);
    float* ss = (float*)(sm + kASS);

    const int qi  = gridDim.x - 1 - blockIdx.x;   // big tiles first
    const int bh  = blockIdx.y;
    const int tid = threadIdx.x;
    const int warp = tid >> 5, lane = tid & 31;
    const int q0  = qi * 128;
    const size_t base = (size_t)bh * kSeq * kHeadDim;

    auto loadKV = [&](int kt, int b) {
        const int k0 = kt * 64;
        char* kv = sm + b * kKVBuf;
        __nv_bfloat16* skh = (__nv_bfloat16*)(kv);
        __nv_bfloat16* skl = (__nv_bfloat16*)(kv + 9216);
        __nv_bfloat16* svh = (__nv_bfloat16*)(kv + 18432);
        __nv_bfloat16* svl = (__nv_bfloat16*)(kv + 27648);
#pragma unroll
        for (int i = 0; i < 2; i++) {
            const int idx = i * 256 + tid;
            const int r = idx >> 3, c8 = (idx & 7) * 8;
            const size_t g = base + (size_t)(k0 + r) * kHeadDim + c8;
            const int so = r * 72 + c8;
            __pipeline_memcpy_async(skh + so, g_kh2 + g, 16);
            __pipeline_memcpy_async(skl + so, g_kl2 + g, 16);
            __pipeline_memcpy_async(svh + so, g_vh2 + g, 16);
            __pipeline_memcpy_async(svl + so, g_vl2 + g, 16);
        }
        __pipeline_commit();
    };

    wmma::fragment<wmma::matrix_a, 16, 16, 16, __nv_bfloat16, wmma::row_major> fqh[4], fql[4];
#pragma unroll
    for (int kk = 0; kk < 4; kk++) {
        const size_t qo = base + (size_t)(q0 + warp * 16) * kHeadDim + kk * 16;
        wmma::load_matrix_sync(fqh[kk], g_qh2 + qo, kHeadDim);
        wmma::load_matrix_sync(fql[kk], g_ql2 + qo, kHeadDim);
    }

    wmma::fragment<wmma::accumulator, 16, 16, 16, float> oacc[4];
#pragma unroll
    for (int nt4 = 0; nt4 < 4; nt4++) wmma::fill_fragment(oacc[nt4], 0.0f);

    const int rr   = lane >> 1;
    const int row  = warp * 16 + rr;
    const int qg   = q0 + row;
    const int c0l  = (lane & 1) * 32;
    float* swS = ss + warp * 16 * 68;
    float lacc = 0.f;

    const int ntiles = 2 * qi + 2;
    loadKV(0, 0);

    for (int kt = 0; kt < ntiles; kt++) {
        const int k0  = kt * 64;
        const int buf = kt & 1;
        char* kv = sm + buf * kKVBuf;
        const __nv_bfloat16* skh = (const __nv_bfloat16*)(kv);
        const __nv_bfloat16* skl = (const __nv_bfloat16*)(kv + 9216);
        const __nv_bfloat16* svh = (const __nv_bfloat16*)(kv + 18432);
        const __nv_bfloat16* svl = (const __nv_bfloat16*)(kv + 27648);

        __pipeline_wait_prior(0);
        __syncthreads();
        if (kt + 1 < ntiles) loadKV(kt + 1, buf ^ 1);

        // S = Q K^T
#pragma unroll
        for (int nt4 = 0; nt4 < 4; nt4++) {
            wmma::fragment<wmma::accumulator, 16, 16, 16, float> sacc;
            wmma::fill_fragment(sacc, 0.0f);
#pragma unroll
            for (int kk = 0; kk < 4; kk++) {
                wmma::fragment<wmma::matrix_b, 16, 16, 16, __nv_bfloat16, wmma::col_major> fbh, fbl;
                wmma::load_matrix_sync(fbh, skh + (nt4 * 16) * 72 + kk * 16, 72);
                wmma::load_matrix_sync(fbl, skl + (nt4 * 16) * 72 + kk * 16, 72);
                wmma::mma_sync(sacc, fqh[kk], fbh, sacc);
                wmma::mma_sync(sacc, fqh[kk], fbl, sacc);
                wmma::mma_sync(sacc, fql[kk], fbh, sacc);
            }
            wmma::store_matrix_sync(swS + nt4 * 16, sacc, 68, wmma::mem_row_major);
        }
        __syncwarp();

        // mask + exp + row-sum + split P
#pragma unroll
        for (int c = 0; c < 32; c++) {
            const int cc = c0l + c;
            const float sv = swS[rr * 68 + cc];
            const int kg = k0 + cc;
            const float p = (kg <= qg) ? __expf(sv * 0.125f) : 0.f;
            lacc += p;
            __nv_bfloat16 hi, lo;
            bf16_split(p, hi, lo);
            ph[row * 72 + cc] = hi;
            pl[row * 72 + cc] = lo;
        }
        __syncwarp();

        // O += P V
#pragma unroll
        for (int kk = 0; kk < 4; kk++) {
            wmma::fragment<wmma::matrix_a, 16, 16, 16, __nv_bfloat16, wmma::row_major> fph, fpl;
            wmma::load_matrix_sync(fph, ph + (warp * 16) * 72 + kk * 16, 72);
            wmma::load_matrix_sync(fpl, pl + (warp * 16) * 72 + kk * 16, 72);
#pragma unroll
            for (int nt4 = 0; nt4 < 4; nt4++) {
                wmma::fragment<wmma::matrix_b, 16, 16, 16, __nv_bfloat16, wmma::row_major> fvh, fvl;
                wmma::load_matrix_sync(fvh, svh + (kk * 16) * 72 + nt4 * 16, 72);
                wmma::load_matrix_sync(fvl, svl + (kk * 16) * 72 + nt4 * 16, 72);
                wmma::mma_sync(oacc[nt4], fph, fvh, oacc[nt4]);
                wmma::mma_sync(oacc[nt4], fph, fvl, oacc[nt4]);
                wmma::mma_sync(oacc[nt4], fpl, fvh, oacc[nt4]);
            }
        }
    }

    // epilogue: O/l -> split bf16 att
#pragma unroll
    for (int nt4 = 0; nt4 < 4; nt4++)
        wmma::store_matrix_sync(swS + nt4 * 16, oacc[nt4], 68, wmma::mem_row_major);
    __syncwarp();

    const float ltot = lacc + __shfl_xor_sync(0xffffffffu, lacc, 1);
    const float inv = 1.f / ltot;
    const int b = bh >> 4, h = bh & 15;
    const size_t obase = ((size_t)(b * kSeq + qg)) * kEmbed + h * kHeadDim;
#pragma unroll
    for (int c = 0; c < 32; c++) {
        const int cc = c0l + c;
        const float val = swS[rr * 68 + cc] * inv;
        __nv_bfloat16 hi, lo;
        bf16_split(val, hi, lo);
        g_atth[obase + cc] = hi;
        g_attl[obase + cc] = lo;
    }
}

// ======================= launch =======================
extern "C" void kernel_launch(void* const* d_in, const int* in_sizes, int n_in,
                              void* d_out, int out_size) {
    const float* x  = (const float*)d_in[0];
    const float* Wq = (const float*)d_in[1];
    const float* Wk = (const float*)d_in[2];
    const float* Wv = (const float*)d_in[3];
    const float* bq = (const float*)d_in[4];
    const float* bk = (const float*)d_in[5];
    const float* bv = (const float*)d_in[6];
    const float* Wp = (const float*)d_in[7];
    const float* bp = (const float*)d_in[8];
    float* out = (float*)d_out;

    cudaFuncSetAttribute(gemm_wmma_kernel, cudaFuncAttributeMaxDynamicSharedMemorySize, kGemmSmem);
    cudaFuncSetAttribute(attn_wmma_kernel, cudaFuncAttributeMaxDynamicSharedMemorySize, kAttnSmem);

    convert_x_kernel<<<(kRows * kEmbed + 255) / 256, 256>>>(x);
    pack_qkv_kernel<<<(kEmbed * kQkvN + 255) / 256, 256>>>(Wq, Wk, Wv, bq, bk, bv);
    pack_wp_kernel<<<(kEmbed * kEmbed + 255) / 256, 256>>>(Wp);

    // QKV projection: [8192,1024] x [1024,3072] -> split bf16 q/k/v
    gemm_wmma_kernel<<<dim3(kQkvN / 128, kRows / 128), 512, kGemmSmem>>>(nullptr, nullptr, 0);

    // causal attention on tensor cores
    attn_wmma_kernel<<<dim3(kSeq / 128, kBatch * kHeads), 256, kAttnSmem>>>();

    // output projection: [8192,1024] x [1024,1024] + bias
    gemm_wmma_kernel<<<dim3(kEmbed / 128, kRows / 128), 512, kGemmSmem>>>(bp, out, 1);
}

// round 8
// speedup vs baseline: 1.1359x; 1.1359x over previous
#include <cuda_runtime.h>
#include <cuda_bf16.h>
#include <cuda_pipeline.h>
#include <mma.h>
#include <math.h>

using namespace nvcuda;

constexpr int kEmbed   = 1024;
constexpr int kHeads   = 16;
constexpr int kHeadDim = 64;
constexpr int kSeq     = 2048;
constexpr int kBatch   = 4;
constexpr int kQkvN    = 3 * kEmbed;          // 3072
constexpr int kRows    = kBatch * kSeq;       // 8192
constexpr int kBHT     = kBatch * kHeads * kSeq * kHeadDim;

// -------- scratch (static device globals; no runtime allocation) --------
__device__ __align__(128) __nv_bfloat16 g_xh[kRows * kEmbed];
__device__ __align__(128) __nv_bfloat16 g_xl[kRows * kEmbed];
__device__ __align__(128) __nv_bfloat16 g_wqkvh[kEmbed * kQkvN];
__device__ __align__(128) __nv_bfloat16 g_wqkvl[kEmbed * kQkvN];
__device__ __align__(128) float g_bqkv[kQkvN];
__device__ __align__(128) __nv_bfloat16 g_qh2[kBHT];   // q pre-scaled by 0.125
__device__ __align__(128) __nv_bfloat16 g_ql2[kBHT];
__device__ __align__(128) __nv_bfloat16 g_kh2[kBHT];
__device__ __align__(128) __nv_bfloat16 g_kl2[kBHT];
__device__ __align__(128) __nv_bfloat16 g_vh2[kBHT];
__device__ __align__(128) __nv_bfloat16 g_vl2[kBHT];
__device__ __align__(128) __nv_bfloat16 g_atth[kRows * kEmbed];
__device__ __align__(128) __nv_bfloat16 g_attl[kRows * kEmbed];
__device__ __align__(128) __nv_bfloat16 g_wph[kEmbed * kEmbed];
__device__ __align__(128) __nv_bfloat16 g_wpl[kEmbed * kEmbed];

// ======================= conversion / packing =======================
__device__ __forceinline__ void bf16_split(float v, __nv_bfloat16& hi, __nv_bfloat16& lo) {
    hi = __float2bfloat16(v);
    lo = __float2bfloat16(v - __bfloat162float(hi));
}

__global__ void convert_x_kernel(const float* __restrict__ x) {
    int idx = blockIdx.x * blockDim.x + threadIdx.x;
    if (idx < kRows * kEmbed) {
        __nv_bfloat16 h, l;
        bf16_split(x[idx], h, l);
        g_xh[idx] = h; g_xl[idx] = l;
    }
}

__global__ void pack_qkv_kernel(const float* __restrict__ Wq, const float* __restrict__ Wk,
                                const float* __restrict__ Wv, const float* __restrict__ bq,
                                const float* __restrict__ bk, const float* __restrict__ bv) {
    int idx = blockIdx.x * blockDim.x + threadIdx.x;
    if (idx < kEmbed * kQkvN) {
        int e = idx / kQkvN;
        int n = idx % kQkvN;
        int which = n >> 10;
        int hd    = n & 1023;
        int h = hd >> 6, d = hd & 63;
        const float* W = (which == 0) ? Wq : (which == 1) ? Wk : Wv;
        float v = W[((size_t)h * kEmbed + e) * kHeadDim + d];
        __nv_bfloat16 hi, lo;
        bf16_split(v, hi, lo);
        g_wqkvh[idx] = hi; g_wqkvl[idx] = lo;
    }
    if (idx < kQkvN) {
        int which = idx >> 10;
        int hd    = idx & 1023;
        const float* bb = (which == 0) ? bq : (which == 1) ? bk : bv;
        g_bqkv[idx] = bb[hd];
    }
}

__global__ void pack_wp_kernel(const float* __restrict__ Wp) {
    int idx = blockIdx.x * blockDim.x + threadIdx.x;
    if (idx < kEmbed * kEmbed) {
        __nv_bfloat16 hi, lo;
        bf16_split(Wp[idx], hi, lo);
        g_wph[idx] = hi; g_wpl[idx] = lo;
    }
}

// ======================= bf16-split WMMA GEMM =======================
// acc += Ah*Bh + Ah*Bl + Al*Bh. Block 128x128, BK=32, cp.async 3-stage,
// 256 threads / 8 warps (2x4), warp tile 64x32. Direct fragment epilogue.
constexpr int kGAh = 0;                      // [128][40] bf16
constexpr int kGAl = 10240;
constexpr int kGBh = 20480;                  // [32][136] bf16
constexpr int kGBl = 29184;
constexpr int kGStage = 37888;
constexpr int kGemmSmem = 3 * kGStage;       // 113664

__global__ __launch_bounds__(256, 1)
void gemm_wmma_kernel(const float* __restrict__ bias_arg, float* __restrict__ outp, int mode) {
    extern __shared__ char sm[];

    const int N = (mode == 0) ? kQkvN : kEmbed;
    const __nv_bfloat16* Ah = (mode == 0) ? g_xh : g_atth;
    const __nv_bfloat16* Al = (mode == 0) ? g_xl : g_attl;
    const __nv_bfloat16* Bh = (mode == 0) ? g_wqkvh : g_wph;
    const __nv_bfloat16* Bl = (mode == 0) ? g_wqkvl : g_wpl;
    const float* bias = (mode == 0) ? g_bqkv : bias_arg;

    const int tid  = threadIdx.x;
    const int warp = tid >> 5, lane = tid & 31;
    const int wm   = warp >> 2, wn = warp & 3;
    const int bm   = blockIdx.y * 128;
    const int bn   = blockIdx.x * 128;

    auto loadStage = [&](int kt, int s) {
        const int k0 = kt * 32;
        char* st = sm + s * kGStage;
        __nv_bfloat16* sAh = (__nv_bfloat16*)(st + kGAh);
        __nv_bfloat16* sAl = (__nv_bfloat16*)(st + kGAl);
        __nv_bfloat16* sBh = (__nv_bfloat16*)(st + kGBh);
        __nv_bfloat16* sBl = (__nv_bfloat16*)(st + kGBl);
#pragma unroll
        for (int i = 0; i < 2; i++) {
            const int idx = i * 256 + tid;
            const int ar = idx >> 2, ac = (idx & 3) * 8;
            const size_t asrc = (size_t)(bm + ar) * kEmbed + k0 + ac;
            __pipeline_memcpy_async(sAh + ar * 40 + ac, Ah + asrc, 16);
            __pipeline_memcpy_async(sAl + ar * 40 + ac, Al + asrc, 16);
            const int br = idx >> 4, bc = (idx & 15) * 8;
            const size_t bsrc = (size_t)(k0 + br) * N + bn + bc;
            __pipeline_memcpy_async(sBh + br * 136 + bc, Bh + bsrc, 16);
            __pipeline_memcpy_async(sBl + br * 136 + bc, Bl + bsrc, 16);
        }
        __pipeline_commit();
    };

    wmma::fragment<wmma::accumulator, 16, 16, 16, float> acc[4][2];
#pragma unroll
    for (int mi = 0; mi < 4; mi++)
#pragma unroll
        for (int ni = 0; ni < 2; ni++) wmma::fill_fragment(acc[mi][ni], 0.0f);

    constexpr int NT = kEmbed / 32;
    loadStage(0, 0);
    loadStage(1, 1);

    for (int kt = 0; kt < NT; kt++) {
        if (kt < NT - 2) __pipeline_wait_prior(1);
        else             __pipeline_wait_prior(0);
        __syncthreads();
        if (kt + 2 < NT) loadStage(kt + 2, (kt + 2) % 3);

        char* st = sm + (kt % 3) * kGStage;
        const __nv_bfloat16* sAh = (const __nv_bfloat16*)(st + kGAh);
        const __nv_bfloat16* sAl = (const __nv_bfloat16*)(st + kGAl);
        const __nv_bfloat16* sBh = (const __nv_bfloat16*)(st + kGBh);
        const __nv_bfloat16* sBl = (const __nv_bfloat16*)(st + kGBl);

#pragma unroll
        for (int kk = 0; kk < 2; kk++) {
            wmma::fragment<wmma::matrix_a, 16, 16, 16, __nv_bfloat16, wmma::row_major> fa[4], fal[4];
            wmma::fragment<wmma::matrix_b, 16, 16, 16, __nv_bfloat16, wmma::row_major> fb[2], fbl[2];
#pragma unroll
            for (int mi = 0; mi < 4; mi++) {
                wmma::load_matrix_sync(fa[mi],  sAh + (wm * 64 + mi * 16) * 40 + kk * 16, 40);
                wmma::load_matrix_sync(fal[mi], sAl + (wm * 64 + mi * 16) * 40 + kk * 16, 40);
            }
#pragma unroll
            for (int ni = 0; ni < 2; ni++) {
                wmma::load_matrix_sync(fb[ni],  sBh + (kk * 16) * 136 + wn * 32 + ni * 16, 136);
                wmma::load_matrix_sync(fbl[ni], sBl + (kk * 16) * 136 + wn * 32 + ni * 16, 136);
            }
#pragma unroll
            for (int mi = 0; mi < 4; mi++)
#pragma unroll
                for (int ni = 0; ni < 2; ni++) {
                    wmma::mma_sync(acc[mi][ni], fa[mi],  fb[ni],  acc[mi][ni]);
                    wmma::mma_sync(acc[mi][ni], fa[mi],  fbl[ni], acc[mi][ni]);
                    wmma::mma_sync(acc[mi][ni], fal[mi], fb[ni],  acc[mi][ni]);
                }
        }
    }

    // direct fragment epilogue (sm_80+ accumulator layout):
    // x[i]: row = lane>>2 + ((i&2)?8:0), col = (lane&3)*2 + (i&1) + ((i&4)?8:0)
#pragma unroll
    for (int mi = 0; mi < 4; mi++) {
#pragma unroll
        for (int ni = 0; ni < 2; ni++) {
#pragma unroll
            for (int i2 = 0; i2 < 4; i2++) {
                const int i = 2 * i2;
                const int row = bm + wm * 64 + mi * 16 + (lane >> 2) + ((i & 2) ? 8 : 0);
                const int col = bn + wn * 32 + ni * 16 + (lane & 3) * 2 + ((i & 4) ? 8 : 0);
                float v0 = acc[mi][ni].x[i]     + bias[col];
                float v1 = acc[mi][ni].x[i + 1] + bias[col + 1];
                if (mode == 0) {
                    const int which = col >> 10, hd = col & 1023;
                    const int h = hd >> 6, d = hd & 63;
                    const int b = row >> 11, t = row & 2047;
                    if (which == 0) { v0 *= 0.125f; v1 *= 0.125f; }
                    __nv_bfloat16* dh = (which == 0) ? g_qh2 : ((which == 1) ? g_kh2 : g_vh2);
                    __nv_bfloat16* dl = (which == 0) ? g_ql2 : ((which == 1) ? g_kl2 : g_vl2);
                    const size_t o = (((size_t)(b * kHeads + h) * kSeq) + t) * kHeadDim + d;
                    __nv_bfloat16 h0, l0, h1, l1;
                    bf16_split(v0, h0, l0); bf16_split(v1, h1, l1);
                    __nv_bfloat162 ph2; ph2.x = h0; ph2.y = h1;
                    __nv_bfloat162 pl2; pl2.x = l0; pl2.y = l1;
                    *(__nv_bfloat162*)(dh + o) = ph2;
                    *(__nv_bfloat162*)(dl + o) = pl2;
                } else {
                    float2 vv; vv.x = v0; vv.y = v1;
                    *(float2*)(outp + (size_t)row * kEmbed + col) = vv;
                }
            }
        }
    }
}

// ======================= WMMA causal attention =======================
// 256 threads, 128 q-rows/CTA (warp owns 16), kv tile 64, cp.async double buffer.
// Register-resident softmax on accumulator fragments; O normalized from fragments.
constexpr int kKVBuf  = 4 * 9216;            // kh,kl,vh,vl each bf16[64][72]
constexpr int kAPH    = 2 * kKVBuf;          // 73728, bf16[128][72]
constexpr int kAPL    = kAPH + 18432;        // 92160
constexpr int kAttnSmem = kAPL + 18432;      // 110592

__global__ __launch_bounds__(256)
void attn_wmma_kernel() {
    extern __shared__ char sm[];
    __nv_bfloat16* ph = (__nv_bfloat16*)(sm + kAPH);
    __nv_bfloat16* pl = (__nv_bfloat16*)(sm + kAPL);

    const int qi  = gridDim.x - 1 - blockIdx.x;   // big tiles first
    const int bh  = blockIdx.y;
    const int tid = threadIdx.x;
    const int warp = tid >> 5, lane = tid & 31;
    const int q0  = qi * 128;
    const size_t base = (size_t)bh * kSeq * kHeadDim;

    auto loadKV = [&](int kt, int b) {
        const int k0 = kt * 64;
        char* kv = sm + b * kKVBuf;
        __nv_bfloat16* skh = (__nv_bfloat16*)(kv);
        __nv_bfloat16* skl = (__nv_bfloat16*)(kv + 9216);
        __nv_bfloat16* svh = (__nv_bfloat16*)(kv + 18432);
        __nv_bfloat16* svl = (__nv_bfloat16*)(kv + 27648);
#pragma unroll
        for (int i = 0; i < 2; i++) {
            const int idx = i * 256 + tid;
            const int r = idx >> 3, c8 = (idx & 7) * 8;
            const size_t g = base + (size_t)(k0 + r) * kHeadDim + c8;
            const int so = r * 72 + c8;
            __pipeline_memcpy_async(skh + so, g_kh2 + g, 16);
            __pipeline_memcpy_async(skl + so, g_kl2 + g, 16);
            __pipeline_memcpy_async(svh + so, g_vh2 + g, 16);
            __pipeline_memcpy_async(svl + so, g_vl2 + g, 16);
        }
        __pipeline_commit();
    };

    wmma::fragment<wmma::matrix_a, 16, 16, 16, __nv_bfloat16, wmma::row_major> fqh[4], fql[4];
#pragma unroll
    for (int kk = 0; kk < 4; kk++) {
        const size_t qo = base + (size_t)(q0 + warp * 16) * kHeadDim + kk * 16;
        wmma::load_matrix_sync(fqh[kk], g_qh2 + qo, kHeadDim);
        wmma::load_matrix_sync(fql[kk], g_ql2 + qo, kHeadDim);
    }

    wmma::fragment<wmma::accumulator, 16, 16, 16, float> oacc[4];
#pragma unroll
    for (int nt4 = 0; nt4 < 4; nt4++) wmma::fill_fragment(oacc[nt4], 0.0f);

    // thread owns rows r0 = warp*16 + lane>>2 and r0+8 (fragment layout)
    const int rlow  = warp * 16 + (lane >> 2);
    const int qglow = q0 + rlow;
    float lacc0 = 0.f, lacc1 = 0.f;    // row sums for rlow, rlow+8

    const int ntiles = 2 * qi + 2;
    loadKV(0, 0);

    for (int kt = 0; kt < ntiles; kt++) {
        const int k0  = kt * 64;
        const int buf = kt & 1;
        char* kv = sm + buf * kKVBuf;
        const __nv_bfloat16* skh = (const __nv_bfloat16*)(kv);
        const __nv_bfloat16* skl = (const __nv_bfloat16*)(kv + 9216);
        const __nv_bfloat16* svh = (const __nv_bfloat16*)(kv + 18432);
        const __nv_bfloat16* svl = (const __nv_bfloat16*)(kv + 27648);

        __pipeline_wait_prior(0);
        __syncthreads();
        if (kt + 1 < ntiles) loadKV(kt + 1, buf ^ 1);

        // S = Q K^T, softmax in registers, P -> smem split bf16
#pragma unroll
        for (int nt4 = 0; nt4 < 4; nt4++) {
            wmma::fragment<wmma::accumulator, 16, 16, 16, float> sacc;
            wmma::fill_fragment(sacc, 0.0f);
#pragma unroll
            for (int kk = 0; kk < 4; kk++) {
                wmma::fragment<wmma::matrix_b, 16, 16, 16, __nv_bfloat16, wmma::col_major> fbh, fbl;
                wmma::load_matrix_sync(fbh, skh + (nt4 * 16) * 72 + kk * 16, 72);
                wmma::load_matrix_sync(fbl, skl + (nt4 * 16) * 72 + kk * 16, 72);
                wmma::mma_sync(sacc, fqh[kk], fbh, sacc);
                wmma::mma_sync(sacc, fqh[kk], fbl, sacc);
                wmma::mma_sync(sacc, fql[kk], fbh, sacc);
            }
#pragma unroll
            for (int i2 = 0; i2 < 4; i2++) {
                const int i = 2 * i2;
                const int rl   = rlow + ((i & 2) ? 8 : 0);
                const int qg   = qglow + ((i & 2) ? 8 : 0);
                const int colb = nt4 * 16 + (lane & 3) * 2 + ((i & 4) ? 8 : 0);
                const int kg   = k0 + colb;
                const float p0 = (kg     <= qg) ? __expf(sacc.x[i])     : 0.f;
                const float p1 = (kg + 1 <= qg) ? __expf(sacc.x[i + 1]) : 0.f;
                if (i & 2) lacc1 += p0 + p1; else lacc0 += p0 + p1;
                __nv_bfloat16 h0, l0, h1, l1;
                bf16_split(p0, h0, l0); bf16_split(p1, h1, l1);
                __nv_bfloat162 hh; hh.x = h0; hh.y = h1;
                __nv_bfloat162 ll; ll.x = l0; ll.y = l1;
                *(__nv_bfloat162*)(ph + rl * 72 + colb) = hh;
                *(__nv_bfloat162*)(pl + rl * 72 + colb) = ll;
            }
        }
        __syncwarp();

        // O += P V
#pragma unroll
        for (int kk = 0; kk < 4; kk++) {
            wmma::fragment<wmma::matrix_a, 16, 16, 16, __nv_bfloat16, wmma::row_major> fph, fpl;
            wmma::load_matrix_sync(fph, ph + (warp * 16) * 72 + kk * 16, 72);
            wmma::load_matrix_sync(fpl, pl + (warp * 16) * 72 + kk * 16, 72);
#pragma unroll
            for (int nt4 = 0; nt4 < 4; nt4++) {
                wmma::fragment<wmma::matrix_b, 16, 16, 16, __nv_bfloat16, wmma::row_major> fvh, fvl;
                wmma::load_matrix_sync(fvh, svh + (kk * 16) * 72 + nt4 * 16, 72);
                wmma::load_matrix_sync(fvl, svl + (kk * 16) * 72 + nt4 * 16, 72);
                wmma::mma_sync(oacc[nt4], fph, fvh, oacc[nt4]);
                wmma::mma_sync(oacc[nt4], fph, fvl, oacc[nt4]);
                wmma::mma_sync(oacc[nt4], fpl, fvh, oacc[nt4]);
            }
        }
    }

    // row-sum reduce across the 4 lanes sharing a row
    lacc0 += __shfl_xor_sync(0xffffffffu, lacc0, 1);
    lacc0 += __shfl_xor_sync(0xffffffffu, lacc0, 2);
    lacc1 += __shfl_xor_sync(0xffffffffu, lacc1, 1);
    lacc1 += __shfl_xor_sync(0xffffffffu, lacc1, 2);
    const float inv0 = 1.f / lacc0;
    const float inv1 = 1.f / lacc1;

    // normalized O direct from fragments -> split bf16 att
    const int b = bh >> 4, h = bh & 15;
#pragma unroll
    for (int nt4 = 0; nt4 < 4; nt4++) {
#pragma unroll
        for (int i2 = 0; i2 < 4; i2++) {
            const int i = 2 * i2;
            const int qg   = qglow + ((i & 2) ? 8 : 0);
            const float inv = (i & 2) ? inv1 : inv0;
            const int colb = nt4 * 16 + (lane & 3) * 2 + ((i & 4) ? 8 : 0);
            const float v0 = oacc[nt4].x[i]     * inv;
            const float v1 = oacc[nt4].x[i + 1] * inv;
            __nv_bfloat16 h0, l0, h1, l1;
            bf16_split(v0, h0, l0); bf16_split(v1, h1, l1);
            __nv_bfloat162 hh; hh.x = h0; hh.y = h1;
            __nv_bfloat162 ll; ll.x = l0; ll.y = l1;
            const size_t o = ((size_t)(b * kSeq + qg)) * kEmbed + h * kHeadDim + colb;
            *(__nv_bfloat162*)(g_atth + o) = hh;
            *(__nv_bfloat162*)(g_attl + o) = ll;
        }
    }
}

// ======================= launch =======================
extern "C" void kernel_launch(void* const* d_in, const int* in_sizes, int n_in,
                              void* d_out, int out_size) {
    const float* x  = (const float*)d_in[0];
    const float* Wq = (const float*)d_in[1];
    const float* Wk = (const float*)d_in[2];
    const float* Wv = (const float*)d_in[3];
    const float* bq = (const float*)d_in[4];
    const float* bk = (const float*)d_in[5];
    const float* bv = (const float*)d_in[6];
    const float* Wp = (const float*)d_in[7];
    const float* bp = (const float*)d_in[8];
    float* out = (float*)d_out;

    cudaFuncSetAttribute(gemm_wmma_kernel, cudaFuncAttributeMaxDynamicSharedMemorySize, kGemmSmem);
    cudaFuncSetAttribute(attn_wmma_kernel, cudaFuncAttributeMaxDynamicSharedMemorySize, kAttnSmem);

    convert_x_kernel<<<(kRows * kEmbed + 255) / 256, 256>>>(x);
    pack_qkv_kernel<<<(kEmbed * kQkvN + 255) / 256, 256>>>(Wq, Wk, Wv, bq, bk, bv);
    pack_wp_kernel<<<(kEmbed * kEmbed + 255) / 256, 256>>>(Wp);

    // QKV projection: [8192,1024] x [1024,3072] -> split bf16 q/k/v (q pre-scaled)
    gemm_wmma_kernel<<<dim3(kQkvN / 128, kRows / 128), 256, kGemmSmem>>>(nullptr, nullptr, 0);

    // causal attention on tensor cores
    attn_wmma_kernel<<<dim3(kSeq / 128, kBatch * kHeads), 256, kAttnSmem>>>();

    // output projection: [8192,1024] x [1024,1024] + bias
    gemm_wmma_kernel<<<dim3(kEmbed / 128, kRows / 128), 256, kGemmSmem>>>(bp, out, 1);
}

// round 9
// speedup vs baseline: 1.4934x; 1.3148x over previous
#include <cuda_runtime.h>
#include <cuda_bf16.h>
#include <cuda_fp16.h>
#include <cuda_pipeline.h>
#include <mma.h>
#include <math.h>

using namespace nvcuda;

constexpr int kEmbed   = 1024;
constexpr int kHeads   = 16;
constexpr int kHeadDim = 64;
constexpr int kSeq     = 2048;
constexpr int kBatch   = 4;
constexpr int kQkvN    = 3 * kEmbed;          // 3072
constexpr int kRows    = kBatch * kSeq;       // 8192
constexpr int kBHT     = kBatch * kHeads * kSeq * kHeadDim;

// -------- scratch (static device globals; no runtime allocation) --------
__device__ __align__(128) __nv_bfloat16 g_xh[kRows * kEmbed];
__device__ __align__(128) __nv_bfloat16 g_xl[kRows * kEmbed];
__device__ __align__(128) __nv_bfloat16 g_wqkvh[kEmbed * kQkvN];
__device__ __align__(128) __nv_bfloat16 g_wqkvl[kEmbed * kQkvN];
__device__ __align__(128) float g_bqkv[kQkvN];
// attention operands in fp16: q split-2 (pre-scaled by 0.125), k/v single
__device__ __align__(128) __half g_qh2[kBHT];
__device__ __align__(128) __half g_ql2[kBHT];
__device__ __align__(128) __half g_kh2[kBHT];
__device__ __align__(128) __half g_vh2[kBHT];
__device__ __align__(128) __nv_bfloat16 g_atth[kRows * kEmbed];
__device__ __align__(128) __nv_bfloat16 g_attl[kRows * kEmbed];
__device__ __align__(128) __nv_bfloat16 g_wph[kEmbed * kEmbed];
__device__ __align__(128) __nv_bfloat16 g_wpl[kEmbed * kEmbed];

// ======================= conversion / packing =======================
__device__ __forceinline__ void bf16_split(float v, __nv_bfloat16& hi, __nv_bfloat16& lo) {
    hi = __float2bfloat16(v);
    lo = __float2bfloat16(v - __bfloat162float(hi));
}
__device__ __forceinline__ void fp16_split(float v, __half& hi, __half& lo) {
    hi = __float2half(v);
    lo = __float2half(v - __half2float(hi));
}

__global__ void convert_x_kernel(const float* __restrict__ x) {
    int idx = blockIdx.x * blockDim.x + threadIdx.x;
    if (idx < kRows * kEmbed) {
        __nv_bfloat16 h, l;
        bf16_split(x[idx], h, l);
        g_xh[idx] = h; g_xl[idx] = l;
    }
}

__global__ void pack_qkv_kernel(const float* __restrict__ Wq, const float* __restrict__ Wk,
                                const float* __restrict__ Wv, const float* __restrict__ bq,
                                const float* __restrict__ bk, const float* __restrict__ bv) {
    int idx = blockIdx.x * blockDim.x + threadIdx.x;
    if (idx < kEmbed * kQkvN) {
        int e = idx / kQkvN;
        int n = idx % kQkvN;
        int which = n >> 10;
        int hd    = n & 1023;
        int h = hd >> 6, d = hd & 63;
        const float* W = (which == 0) ? Wq : (which == 1) ? Wk : Wv;
        float v = W[((size_t)h * kEmbed + e) * kHeadDim + d];
        __nv_bfloat16 hi, lo;
        bf16_split(v, hi, lo);
        g_wqkvh[idx] = hi; g_wqkvl[idx] = lo;
    }
    if (idx < kQkvN) {
        int which = idx >> 10;
        int hd    = idx & 1023;
        const float* bb = (which == 0) ? bq : (which == 1) ? bk : bv;
        g_bqkv[idx] = bb[hd];
    }
}

__global__ void pack_wp_kernel(const float* __restrict__ Wp) {
    int idx = blockIdx.x * blockDim.x + threadIdx.x;
    if (idx < kEmbed * kEmbed) {
        __nv_bfloat16 hi, lo;
        bf16_split(Wp[idx], hi, lo);
        g_wph[idx] = hi; g_wpl[idx] = lo;
    }
}

// ======================= bf16-split WMMA GEMM =======================
// acc += Ah*Bh + Ah*Bl + Al*Bh. Block 64x128, BK=32, cp.async 3-stage,
// 256 threads / 8 warps (2m x 4n), warp tile 32x32, 2 CTAs/SM.
constexpr int kGAh = 0;                      // [64][40] bf16 = 5120
constexpr int kGAl = 5120;
constexpr int kGBh = 10240;                  // [32][136] bf16 = 8704
constexpr int kGBl = 18944;
constexpr int kGStage = 27648;
constexpr int kGemmSmem = 3 * kGStage;       // 82944 -> 2 CTAs/SM

__global__ __launch_bounds__(256, 2)
void gemm_wmma_kernel(const float* __restrict__ bias_arg, float* __restrict__ outp, int mode) {
    extern __shared__ char sm[];

    const int N = (mode == 0) ? kQkvN : kEmbed;
    const __nv_bfloat16* Ah = (mode == 0) ? g_xh : g_atth;
    const __nv_bfloat16* Al = (mode == 0) ? g_xl : g_attl;
    const __nv_bfloat16* Bh = (mode == 0) ? g_wqkvh : g_wph;
    const __nv_bfloat16* Bl = (mode == 0) ? g_wqkvl : g_wpl;
    const float* bias = (mode == 0) ? g_bqkv : bias_arg;

    const int tid  = threadIdx.x;
    const int warp = tid >> 5, lane = tid & 31;
    const int wm   = warp >> 2, wn = warp & 3;   // 2 x 4 warp grid
    const int bm   = blockIdx.y * 64;
    const int bn   = blockIdx.x * 128;

    const int ar = tid >> 2,  ac = (tid & 3) * 8;    // A: 64 rows x 32 cols
    const int br = tid >> 4,  bc = (tid & 15) * 8;   // B: 32 rows x 128 cols

    auto loadStage = [&](int kt, int s) {
        const int k0 = kt * 32;
        char* st = sm + s * kGStage;
        __nv_bfloat16* sAh = (__nv_bfloat16*)(st + kGAh);
        __nv_bfloat16* sAl = (__nv_bfloat16*)(st + kGAl);
        __nv_bfloat16* sBh = (__nv_bfloat16*)(st + kGBh);
        __nv_bfloat16* sBl = (__nv_bfloat16*)(st + kGBl);
        const size_t asrc = (size_t)(bm + ar) * kEmbed + k0 + ac;
        __pipeline_memcpy_async(sAh + ar * 40 + ac, Ah + asrc, 16);
        __pipeline_memcpy_async(sAl + ar * 40 + ac, Al + asrc, 16);
        const size_t bsrc = (size_t)(k0 + br) * N + bn + bc;
        __pipeline_memcpy_async(sBh + br * 136 + bc, Bh + bsrc, 16);
        __pipeline_memcpy_async(sBl + br * 136 + bc, Bl + bsrc, 16);
        const size_t bsrc2 = bsrc + 16 * N;
        __pipeline_memcpy_async(sBh + (br + 16) * 136 + bc, Bh + bsrc2, 16);
        __pipeline_memcpy_async(sBl + (br + 16) * 136 + bc, Bl + bsrc2, 16);
        __pipeline_commit();
    };

    wmma::fragment<wmma::accumulator, 16, 16, 16, float> acc[2][2];
#pragma unroll
    for (int mi = 0; mi < 2; mi++)
#pragma unroll
        for (int ni = 0; ni < 2; ni++) wmma::fill_fragment(acc[mi][ni], 0.0f);

    constexpr int NT = kEmbed / 32;
    loadStage(0, 0);
    loadStage(1, 1);

    for (int kt = 0; kt < NT; kt++) {
        if (kt < NT - 2) __pipeline_wait_prior(1);
        else             __pipeline_wait_prior(0);
        __syncthreads();
        if (kt + 2 < NT) loadStage(kt + 2, (kt + 2) % 3);

        char* st = sm + (kt % 3) * kGStage;
        const __nv_bfloat16* sAh = (const __nv_bfloat16*)(st + kGAh);
        const __nv_bfloat16* sAl = (const __nv_bfloat16*)(st + kGAl);
        const __nv_bfloat16* sBh = (const __nv_bfloat16*)(st + kGBh);
        const __nv_bfloat16* sBl = (const __nv_bfloat16*)(st + kGBl);

#pragma unroll
        for (int kk = 0; kk < 2; kk++) {
            wmma::fragment<wmma::matrix_a, 16, 16, 16, __nv_bfloat16, wmma::row_major> fa[2], fal[2];
            wmma::fragment<wmma::matrix_b, 16, 16, 16, __nv_bfloat16, wmma::row_major> fb[2], fbl[2];
#pragma unroll
            for (int mi = 0; mi < 2; mi++) {
                wmma::load_matrix_sync(fa[mi],  sAh + (wm * 32 + mi * 16) * 40 + kk * 16, 40);
                wmma::load_matrix_sync(fal[mi], sAl + (wm * 32 + mi * 16) * 40 + kk * 16, 40);
            }
#pragma unroll
            for (int ni = 0; ni < 2; ni++) {
                wmma::load_matrix_sync(fb[ni],  sBh + (kk * 16) * 136 + wn * 32 + ni * 16, 136);
                wmma::load_matrix_sync(fbl[ni], sBl + (kk * 16) * 136 + wn * 32 + ni * 16, 136);
            }
#pragma unroll
            for (int mi = 0; mi < 2; mi++)
#pragma unroll
                for (int ni = 0; ni < 2; ni++) {
                    wmma::mma_sync(acc[mi][ni], fa[mi],  fb[ni],  acc[mi][ni]);
                    wmma::mma_sync(acc[mi][ni], fa[mi],  fbl[ni], acc[mi][ni]);
                    wmma::mma_sync(acc[mi][ni], fal[mi], fb[ni],  acc[mi][ni]);
                }
        }
    }

    // direct fragment epilogue (sm_80+ accumulator layout)
#pragma unroll
    for (int mi = 0; mi < 2; mi++) {
#pragma unroll
        for (int ni = 0; ni < 2; ni++) {
#pragma unroll
            for (int i2 = 0; i2 < 4; i2++) {
                const int i = 2 * i2;
                const int row = bm + wm * 32 + mi * 16 + (lane >> 2) + ((i & 2) ? 8 : 0);
                const int col = bn + wn * 32 + ni * 16 + (lane & 3) * 2 + ((i & 4) ? 8 : 0);
                float v0 = acc[mi][ni].x[i]     + bias[col];
                float v1 = acc[mi][ni].x[i + 1] + bias[col + 1];
                if (mode == 0) {
                    const int which = col >> 10, hd = col & 1023;
                    const int h = hd >> 6, d = hd & 63;
                    const int b = row >> 11, t = row & 2047;
                    const size_t o = (((size_t)(b * kHeads + h) * kSeq) + t) * kHeadDim + d;
                    if (which == 0) {
                        v0 *= 0.125f; v1 *= 0.125f;
                        __half h0, l0, h1, l1;
                        fp16_split(v0, h0, l0); fp16_split(v1, h1, l1);
                        __half2 hh; hh.x = h0; hh.y = h1;
                        __half2 ll; ll.x = l0; ll.y = l1;
                        *(__half2*)(g_qh2 + o) = hh;
                        *(__half2*)(g_ql2 + o) = ll;
                    } else {
                        __half2 hh; hh.x = __float2half(v0); hh.y = __float2half(v1);
                        __half* dst = (which == 1) ? g_kh2 : g_vh2;
                        *(__half2*)(dst + o) = hh;
                    }
                } else {
                    float2 vv; vv.x = v0; vv.y = v1;
                    *(float2*)(outp + (size_t)row * kEmbed + col) = vv;
                }
            }
        }
    }
}

// ======================= fp16 WMMA causal attention =======================
// 256 threads, 128 q-rows/CTA, kv tile 64, cp.async double buffer.
// S = (qh+ql)*kh (2 MMAs), O += (ph+pl)*vh (2 MMAs). Register softmax.
constexpr int kKVBuf  = 2 * 9216;            // kh, vh each half[64][72]
constexpr int kAPH    = 2 * kKVBuf;          // 36864, half[128][72]
constexpr int kAPL    = kAPH + 18432;        // 55296
constexpr int kAttnSmem = kAPL + 18432;      // 73728

__global__ __launch_bounds__(256)
void attn_wmma_kernel() {
    extern __shared__ char sm[];
    __half* ph = (__half*)(sm + kAPH);
    __half* pl = (__half*)(sm + kAPL);

    const int qi  = gridDim.x - 1 - blockIdx.x;   // big tiles first
    const int bh  = blockIdx.y;
    const int tid = threadIdx.x;
    const int warp = tid >> 5, lane = tid & 31;
    const int q0  = qi * 128;
    const size_t base = (size_t)bh * kSeq * kHeadDim;

    auto loadKV = [&](int kt, int b) {
        const int k0 = kt * 64;
        char* kv = sm + b * kKVBuf;
        __half* skh = (__half*)(kv);
        __half* svh = (__half*)(kv + 9216);
#pragma unroll
        for (int i = 0; i < 2; i++) {
            const int idx = i * 256 + tid;
            const int r = idx >> 3, c8 = (idx & 7) * 8;
            const size_t g = base + (size_t)(k0 + r) * kHeadDim + c8;
            const int so = r * 72 + c8;
            __pipeline_memcpy_async(skh + so, g_kh2 + g, 16);
            __pipeline_memcpy_async(svh + so, g_vh2 + g, 16);
        }
        __pipeline_commit();
    };

    wmma::fragment<wmma::matrix_a, 16, 16, 16, __half, wmma::row_major> fqh[4], fql[4];
#pragma unroll
    for (int kk = 0; kk < 4; kk++) {
        const size_t qo = base + (size_t)(q0 + warp * 16) * kHeadDim + kk * 16;
        wmma::load_matrix_sync(fqh[kk], g_qh2 + qo, kHeadDim);
        wmma::load_matrix_sync(fql[kk], g_ql2 + qo, kHeadDim);
    }

    wmma::fragment<wmma::accumulator, 16, 16, 16, float> oacc[4];
#pragma unroll
    for (int nt4 = 0; nt4 < 4; nt4++) wmma::fill_fragment(oacc[nt4], 0.0f);

    const int rlow  = warp * 16 + (lane >> 2);
    const int qglow = q0 + rlow;
    float lacc0 = 0.f, lacc1 = 0.f;

    const int ntiles = 2 * qi + 2;
    loadKV(0, 0);

    for (int kt = 0; kt < ntiles; kt++) {
        const int k0  = kt * 64;
        const int buf = kt & 1;
        char* kv = sm + buf * kKVBuf;
        const __half* skh = (const __half*)(kv);
        const __half* svh = (const __half*)(kv + 9216);

        __pipeline_wait_prior(0);
        __syncthreads();
        if (kt + 1 < ntiles) loadKV(kt + 1, buf ^ 1);

        // S = Q K^T, softmax in registers, P -> smem split fp16
#pragma unroll
        for (int nt4 = 0; nt4 < 4; nt4++) {
            wmma::fragment<wmma::accumulator, 16, 16, 16, float> sacc;
            wmma::fill_fragment(sacc, 0.0f);
#pragma unroll
            for (int kk = 0; kk < 4; kk++) {
                wmma::fragment<wmma::matrix_b, 16, 16, 16, __half, wmma::col_major> fbh;
                wmma::load_matrix_sync(fbh, skh + (nt4 * 16) * 72 + kk * 16, 72);
                wmma::mma_sync(sacc, fqh[kk], fbh, sacc);
                wmma::mma_sync(sacc, fql[kk], fbh, sacc);
            }
#pragma unroll
            for (int i2 = 0; i2 < 4; i2++) {
                const int i = 2 * i2;
                const int rl   = rlow + ((i & 2) ? 8 : 0);
                const int qg   = qglow + ((i & 2) ? 8 : 0);
                const int colb = nt4 * 16 + (lane & 3) * 2 + ((i & 4) ? 8 : 0);
                const int kg   = k0 + colb;
                const float p0 = (kg     <= qg) ? __expf(sacc.x[i])     : 0.f;
                const float p1 = (kg + 1 <= qg) ? __expf(sacc.x[i + 1]) : 0.f;
                if (i & 2) lacc1 += p0 + p1; else lacc0 += p0 + p1;
                __half h0, l0, h1, l1;
                fp16_split(p0, h0, l0); fp16_split(p1, h1, l1);
                __half2 hh; hh.x = h0; hh.y = h1;
                __half2 ll; ll.x = l0; ll.y = l1;
                *(__half2*)(ph + rl * 72 + colb) = hh;
                *(__half2*)(pl + rl * 72 + colb) = ll;
            }
        }
        __syncwarp();

        // O += P V
#pragma unroll
        for (int kk = 0; kk < 4; kk++) {
            wmma::fragment<wmma::matrix_a, 16, 16, 16, __half, wmma::row_major> fph, fpl;
            wmma::load_matrix_sync(fph, ph + (warp * 16) * 72 + kk * 16, 72);
            wmma::load_matrix_sync(fpl, pl + (warp * 16) * 72 + kk * 16, 72);
#pragma unroll
            for (int nt4 = 0; nt4 < 4; nt4++) {
                wmma::fragment<wmma::matrix_b, 16, 16, 16, __half, wmma::row_major> fvh;
                wmma::load_matrix_sync(fvh, svh + (kk * 16) * 72 + nt4 * 16, 72);
                wmma::mma_sync(oacc[nt4], fph, fvh, oacc[nt4]);
                wmma::mma_sync(oacc[nt4], fpl, fvh, oacc[nt4]);
            }
        }
    }

    lacc0 += __shfl_xor_sync(0xffffffffu, lacc0, 1);
    lacc0 += __shfl_xor_sync(0xffffffffu, lacc0, 2);
    lacc1 += __shfl_xor_sync(0xffffffffu, lacc1, 1);
    lacc1 += __shfl_xor_sync(0xffffffffu, lacc1, 2);
    const float inv0 = 1.f / lacc0;
    const float inv1 = 1.f / lacc1;

    const int b = bh >> 4, h = bh & 15;
#pragma unroll
    for (int nt4 = 0; nt4 < 4; nt4++) {
#pragma unroll
        for (int i2 = 0; i2 < 4; i2++) {
            const int i = 2 * i2;
            const int qg   = qglow + ((i & 2) ? 8 : 0);
            const float inv = (i & 2) ? inv1 : inv0;
            const int colb = nt4 * 16 + (lane & 3) * 2 + ((i & 4) ? 8 : 0);
            const float v0 = oacc[nt4].x[i]     * inv;
            const float v1 = oacc[nt4].x[i + 1] * inv;
            __nv_bfloat16 h0, l0, h1, l1;
            bf16_split(v0, h0, l0); bf16_split(v1, h1, l1);
            __nv_bfloat162 hh; hh.x = h0; hh.y = h1;
            __nv_bfloat162 ll; ll.x = l0; ll.y = l1;
            const size_t o = ((size_t)(b * kSeq + qg)) * kEmbed + h * kHeadDim + colb;
            *(__nv_bfloat162*)(g_atth + o) = hh;
            *(__nv_bfloat162*)(g_attl + o) = ll;
        }
    }
}

// ======================= launch =======================
extern "C" void kernel_launch(void* const* d_in, const int* in_sizes, int n_in,
                              void* d_out, int out_size) {
    const float* x  = (const float*)d_in[0];
    const float* Wq = (const float*)d_in[1];
    const float* Wk = (const float*)d_in[2];
    const float* Wv = (const float*)d_in[3];
    const float* bq = (const float*)d_in[4];
    const float* bk = (const float*)d_in[5];
    const float* bv = (const float*)d_in[6];
    const float* Wp = (const float*)d_in[7];
    const float* bp = (const float*)d_in[8];
    float* out = (float*)d_out;

    cudaFuncSetAttribute(gemm_wmma_kernel, cudaFuncAttributeMaxDynamicSharedMemorySize, kGemmSmem);
    cudaFuncSetAttribute(attn_wmma_kernel, cudaFuncAttributeMaxDynamicSharedMemorySize, kAttnSmem);

    convert_x_kernel<<<(kRows * kEmbed + 255) / 256, 256>>>(x);
    pack_qkv_kernel<<<(kEmbed * kQkvN + 255) / 256, 256>>>(Wq, Wk, Wv, bq, bk, bv);
    pack_wp_kernel<<<(kEmbed * kEmbed + 255) / 256, 256>>>(Wp);

    // QKV projection: [8192,1024] x [1024,3072] -> fp16 q(split)/k/v
    gemm_wmma_kernel<<<dim3(kQkvN / 128, kRows / 64), 256, kGemmSmem>>>(nullptr, nullptr, 0);

    // causal attention on tensor cores (fp16 asymmetric split)
    attn_wmma_kernel<<<dim3(kSeq / 128, kBatch * kHeads), 256, kAttnSmem>>>();

    // output projection: [8192,1024] x [1024,1024] + bias
    gemm_wmma_kernel<<<dim3(kEmbed / 128, kRows / 64), 256, kGemmSmem>>>(bp, out, 1);
}

// round 10
// speedup vs baseline: 2.2642x; 1.5161x over previous
#include <cuda_runtime.h>
#include <cuda_bf16.h>
#include <cuda_fp16.h>
#include <cuda_pipeline.h>
#include <mma.h>
#include <math.h>

using namespace nvcuda;

constexpr int kEmbed   = 1024;
constexpr int kHeads   = 16;
constexpr int kHeadDim = 64;
constexpr int kSeq     = 2048;
constexpr int kBatch   = 4;
constexpr int kQkvN    = 3 * kEmbed;          // 3072
constexpr int kRows    = kBatch * kSeq;       // 8192
constexpr int kBHT     = kBatch * kHeads * kSeq * kHeadDim;

// -------- scratch (static device globals; no runtime allocation) --------
__device__ __align__(128) __half g_xh[kRows * kEmbed];     // x split-2 fp16
__device__ __align__(128) __half g_xl[kRows * kEmbed];
__device__ __align__(128) __half g_wqkv[kEmbed * kQkvN];   // weights single fp16
__device__ __align__(128) float g_bqkv[kQkvN];
// attention operands: q split-2 (pre-scaled by 0.125), k/v single fp16
__device__ __align__(128) __half g_qh2[kBHT];
__device__ __align__(128) __half g_ql2[kBHT];
__device__ __align__(128) __half g_kh2[kBHT];
__device__ __align__(128) __half g_vh2[kBHT];
__device__ __align__(128) __half g_ath[kRows * kEmbed];    // att split-2 fp16
__device__ __align__(128) __half g_atl[kRows * kEmbed];
__device__ __align__(128) __half g_wp[kEmbed * kEmbed];    // single fp16

// ======================= conversion / packing =======================
__device__ __forceinline__ void fp16_split(float v, __half& hi, __half& lo) {
    hi = __float2half(v);
    lo = __float2half(v - __half2float(hi));
}

__global__ void convert_x_kernel(const float* __restrict__ x) {
    int idx = blockIdx.x * blockDim.x + threadIdx.x;
    if (idx < kRows * kEmbed) {
        __half h, l;
        fp16_split(x[idx], h, l);
        g_xh[idx] = h; g_xl[idx] = l;
    }
}

__global__ void pack_qkv_kernel(const float* __restrict__ Wq, const float* __restrict__ Wk,
                                const float* __restrict__ Wv, const float* __restrict__ bq,
                                const float* __restrict__ bk, const float* __restrict__ bv) {
    int idx = blockIdx.x * blockDim.x + threadIdx.x;
    if (idx < kEmbed * kQkvN) {
        int e = idx / kQkvN;
        int n = idx % kQkvN;
        int which = n >> 10;
        int hd    = n & 1023;
        int h = hd >> 6, d = hd & 63;
        const float* W = (which == 0) ? Wq : (which == 1) ? Wk : Wv;
        g_wqkv[idx] = __float2half(W[((size_t)h * kEmbed + e) * kHeadDim + d]);
    }
    if (idx < kQkvN) {
        int which = idx >> 10;
        int hd    = idx & 1023;
        const float* bb = (which == 0) ? bq : (which == 1) ? bk : bv;
        g_bqkv[idx] = bb[hd];
    }
}

__global__ void pack_wp_kernel(const float* __restrict__ Wp) {
    int idx = blockIdx.x * blockDim.x + threadIdx.x;
    if (idx < kEmbed * kEmbed) g_wp[idx] = __float2half(Wp[idx]);
}

// ======================= fp16-split WMMA GEMM =======================
// acc += Ah*B + Al*B (A split-2 fp16, B single fp16). Block 64x128, BK=32,
// cp.async 3-stage, 256 threads / 8 warps (2m x 4n), warp tile 32x32, 2 CTAs/SM.
constexpr int kGAh = 0;                      // [64][40] half = 5120
constexpr int kGAl = 5120;
constexpr int kGB  = 10240;                  // [32][136] half = 8704
constexpr int kGStage = 18944;
constexpr int kGemmSmem = 3 * kGStage;       // 56832 -> 2 CTAs/SM

__global__ __launch_bounds__(256, 2)
void gemm_wmma_kernel(const float* __restrict__ bias_arg, float* __restrict__ outp, int mode) {
    extern __shared__ char sm[];

    const int N = (mode == 0) ? kQkvN : kEmbed;
    const __half* Ah = (mode == 0) ? g_xh : g_ath;
    const __half* Al = (mode == 0) ? g_xl : g_atl;
    const __half* B  = (mode == 0) ? g_wqkv : g_wp;
    const float* bias = (mode == 0) ? g_bqkv : bias_arg;

    const int tid  = threadIdx.x;
    const int warp = tid >> 5, lane = tid & 31;
    const int wm   = warp >> 2, wn = warp & 3;   // 2 x 4 warp grid
    const int bm   = blockIdx.y * 64;
    const int bn   = blockIdx.x * 128;

    const int ar = tid >> 2,  ac = (tid & 3) * 8;    // A: 64 rows x 32 cols
    const int br = tid >> 4,  bc = (tid & 15) * 8;   // B: 32 rows x 128 cols

    auto loadStage = [&](int kt, int s) {
        const int k0 = kt * 32;
        char* st = sm + s * kGStage;
        __half* sAh = (__half*)(st + kGAh);
        __half* sAl = (__half*)(st + kGAl);
        __half* sB  = (__half*)(st + kGB);
        const size_t asrc = (size_t)(bm + ar) * kEmbed + k0 + ac;
        __pipeline_memcpy_async(sAh + ar * 40 + ac, Ah + asrc, 16);
        __pipeline_memcpy_async(sAl + ar * 40 + ac, Al + asrc, 16);
        const size_t bsrc = (size_t)(k0 + br) * N + bn + bc;
        __pipeline_memcpy_async(sB + br * 136 + bc, B + bsrc, 16);
        const size_t bsrc2 = bsrc + (size_t)16 * N;
        __pipeline_memcpy_async(sB + (br + 16) * 136 + bc, B + bsrc2, 16);
        __pipeline_commit();
    };

    wmma::fragment<wmma::accumulator, 16, 16, 16, float> acc[2][2];
#pragma unroll
    for (int mi = 0; mi < 2; mi++)
#pragma unroll
        for (int ni = 0; ni < 2; ni++) wmma::fill_fragment(acc[mi][ni], 0.0f);

    constexpr int NT = kEmbed / 32;
    loadStage(0, 0);
    loadStage(1, 1);

    for (int kt = 0; kt < NT; kt++) {
        if (kt < NT - 2) __pipeline_wait_prior(1);
        else             __pipeline_wait_prior(0);
        __syncthreads();
        if (kt + 2 < NT) loadStage(kt + 2, (kt + 2) % 3);

        char* st = sm + (kt % 3) * kGStage;
        const __half* sAh = (const __half*)(st + kGAh);
        const __half* sAl = (const __half*)(st + kGAl);
        const __half* sB  = (const __half*)(st + kGB);

#pragma unroll
        for (int kk = 0; kk < 2; kk++) {
            wmma::fragment<wmma::matrix_a, 16, 16, 16, __half, wmma::row_major> fa[2], fal[2];
            wmma::fragment<wmma::matrix_b, 16, 16, 16, __half, wmma::row_major> fb[2];
#pragma unroll
            for (int mi = 0; mi < 2; mi++) {
                wmma::load_matrix_sync(fa[mi],  sAh + (wm * 32 + mi * 16) * 40 + kk * 16, 40);
                wmma::load_matrix_sync(fal[mi], sAl + (wm * 32 + mi * 16) * 40 + kk * 16, 40);
            }
#pragma unroll
            for (int ni = 0; ni < 2; ni++)
                wmma::load_matrix_sync(fb[ni], sB + (kk * 16) * 136 + wn * 32 + ni * 16, 136);
#pragma unroll
            for (int mi = 0; mi < 2; mi++)
#pragma unroll
                for (int ni = 0; ni < 2; ni++) {
                    wmma::mma_sync(acc[mi][ni], fa[mi],  fb[ni], acc[mi][ni]);
                    wmma::mma_sync(acc[mi][ni], fal[mi], fb[ni], acc[mi][ni]);
                }
        }
    }

    // direct fragment epilogue (sm_80+ accumulator layout)
#pragma unroll
    for (int mi = 0; mi < 2; mi++) {
#pragma unroll
        for (int ni = 0; ni < 2; ni++) {
#pragma unroll
            for (int i2 = 0; i2 < 4; i2++) {
                const int i = 2 * i2;
                const int row = bm + wm * 32 + mi * 16 + (lane >> 2) + ((i & 2) ? 8 : 0);
                const int col = bn + wn * 32 + ni * 16 + (lane & 3) * 2 + ((i & 4) ? 8 : 0);
                float v0 = acc[mi][ni].x[i]     + bias[col];
                float v1 = acc[mi][ni].x[i + 1] + bias[col + 1];
                if (mode == 0) {
                    const int which = col >> 10, hd = col & 1023;
                    const int h = hd >> 6, d = hd & 63;
                    const int b = row >> 11, t = row & 2047;
                    const size_t o = (((size_t)(b * kHeads + h) * kSeq) + t) * kHeadDim + d;
                    if (which == 0) {
                        v0 *= 0.125f; v1 *= 0.125f;
                        __half h0, l0, h1, l1;
                        fp16_split(v0, h0, l0); fp16_split(v1, h1, l1);
                        __half2 hh; hh.x = h0; hh.y = h1;
                        __half2 ll; ll.x = l0; ll.y = l1;
                        *(__half2*)(g_qh2 + o) = hh;
                        *(__half2*)(g_ql2 + o) = ll;
                    } else {
                        __half2 hh; hh.x = __float2half(v0); hh.y = __float2half(v1);
                        __half* dst = (which == 1) ? g_kh2 : g_vh2;
                        *(__half2*)(dst + o) = hh;
                    }
                } else {
                    float2 vv; vv.x = v0; vv.y = v1;
                    *(float2*)(outp + (size_t)row * kEmbed + col) = vv;
                }
            }
        }
    }
}

// ======================= fp16 WMMA causal attention =======================
// 256 threads, 128 q-rows/CTA, kv tile 64, cp.async double buffer.
// S = (qh+ql)*kh (2 MMAs), O += (ph+pl)*vh (2 MMAs). Register softmax.
constexpr int kKVBuf  = 2 * 9216;            // kh, vh each half[64][72]
constexpr int kAPH    = 2 * kKVBuf;          // 36864, half[128][72]
constexpr int kAPL    = kAPH + 18432;        // 55296
constexpr int kAttnSmem = kAPL + 18432;      // 73728

__global__ __launch_bounds__(256)
void attn_wmma_kernel() {
    extern __shared__ char sm[];
    __half* ph = (__half*)(sm + kAPH);
    __half* pl = (__half*)(sm + kAPL);

    const int qi  = gridDim.x - 1 - blockIdx.x;   // big tiles first
    const int bh  = blockIdx.y;
    const int tid = threadIdx.x;
    const int warp = tid >> 5, lane = tid & 31;
    const int q0  = qi * 128;
    const size_t base = (size_t)bh * kSeq * kHeadDim;

    auto loadKV = [&](int kt, int b) {
        const int k0 = kt * 64;
        char* kv = sm + b * kKVBuf;
        __half* skh = (__half*)(kv);
        __half* svh = (__half*)(kv + 9216);
#pragma unroll
        for (int i = 0; i < 2; i++) {
            const int idx = i * 256 + tid;
            const int r = idx >> 3, c8 = (idx & 7) * 8;
            const size_t g = base + (size_t)(k0 + r) * kHeadDim + c8;
            const int so = r * 72 + c8;
            __pipeline_memcpy_async(skh + so, g_kh2 + g, 16);
            __pipeline_memcpy_async(svh + so, g_vh2 + g, 16);
        }
        __pipeline_commit();
    };

    wmma::fragment<wmma::matrix_a, 16, 16, 16, __half, wmma::row_major> fqh[4], fql[4];
#pragma unroll
    for (int kk = 0; kk < 4; kk++) {
        const size_t qo = base + (size_t)(q0 + warp * 16) * kHeadDim + kk * 16;
        wmma::load_matrix_sync(fqh[kk], g_qh2 + qo, kHeadDim);
        wmma::load_matrix_sync(fql[kk], g_ql2 + qo, kHeadDim);
    }

    wmma::fragment<wmma::accumulator, 16, 16, 16, float> oacc[4];
#pragma unroll
    for (int nt4 = 0; nt4 < 4; nt4++) wmma::fill_fragment(oacc[nt4], 0.0f);

    const int rlow  = warp * 16 + (lane >> 2);
    const int qglow = q0 + rlow;
    float lacc0 = 0.f, lacc1 = 0.f;

    const int ntiles = 2 * qi + 2;
    loadKV(0, 0);

    for (int kt = 0; kt < ntiles; kt++) {
        const int k0  = kt * 64;
        const int buf = kt & 1;
        char* kv = sm + buf * kKVBuf;
        const __half* skh = (const __half*)(kv);
        const __half* svh = (const __half*)(kv + 9216);

        __pipeline_wait_prior(0);
        __syncthreads();
        if (kt + 1 < ntiles) loadKV(kt + 1, buf ^ 1);

        // S = Q K^T, softmax in registers, P -> smem split fp16
#pragma unroll
        for (int nt4 = 0; nt4 < 4; nt4++) {
            wmma::fragment<wmma::accumulator, 16, 16, 16, float> sacc;
            wmma::fill_fragment(sacc, 0.0f);
#pragma unroll
            for (int kk = 0; kk < 4; kk++) {
                wmma::fragment<wmma::matrix_b, 16, 16, 16, __half, wmma::col_major> fbh;
                wmma::load_matrix_sync(fbh, skh + (nt4 * 16) * 72 + kk * 16, 72);
                wmma::mma_sync(sacc, fqh[kk], fbh, sacc);
                wmma::mma_sync(sacc, fql[kk], fbh, sacc);
            }
#pragma unroll
            for (int i2 = 0; i2 < 4; i2++) {
                const int i = 2 * i2;
                const int rl   = rlow + ((i & 2) ? 8 : 0);
                const int qg   = qglow + ((i & 2) ? 8 : 0);
                const int colb = nt4 * 16 + (lane & 3) * 2 + ((i & 4) ? 8 : 0);
                const int kg   = k0 + colb;
                const float p0 = (kg     <= qg) ? __expf(sacc.x[i])     : 0.f;
                const float p1 = (kg + 1 <= qg) ? __expf(sacc.x[i + 1]) : 0.f;
                if (i & 2) lacc1 += p0 + p1; else lacc0 += p0 + p1;
                __half h0, l0, h1, l1;
                fp16_split(p0, h0, l0); fp16_split(p1, h1, l1);
                __half2 hh; hh.x = h0; hh.y = h1;
                __half2 ll; ll.x = l0; ll.y = l1;
                *(__half2*)(ph + rl * 72 + colb) = hh;
                *(__half2*)(pl + rl * 72 + colb) = ll;
            }
        }
        __syncwarp();

        // O += P V
#pragma unroll
        for (int kk = 0; kk < 4; kk++) {
            wmma::fragment<wmma::matrix_a, 16, 16, 16, __half, wmma::row_major> fph, fpl;
            wmma::load_matrix_sync(fph, ph + (warp * 16) * 72 + kk * 16, 72);
            wmma::load_matrix_sync(fpl, pl + (warp * 16) * 72 + kk * 16, 72);
#pragma unroll
            for (int nt4 = 0; nt4 < 4; nt4++) {
                wmma::fragment<wmma::matrix_b, 16, 16, 16, __half, wmma::row_major> fvh;
                wmma::load_matrix_sync(fvh, svh + (kk * 16) * 72 + nt4 * 16, 72);
                wmma::mma_sync(oacc[nt4], fph, fvh, oacc[nt4]);
                wmma::mma_sync(oacc[nt4], fpl, fvh, oacc[nt4]);
            }
        }
    }

    lacc0 += __shfl_xor_sync(0xffffffffu, lacc0, 1);
    lacc0 += __shfl_xor_sync(0xffffffffu, lacc0, 2);
    lacc1 += __shfl_xor_sync(0xffffffffu, lacc1, 1);
    lacc1 += __shfl_xor_sync(0xffffffffu, lacc1, 2);
    const float inv0 = 1.f / lacc0;
    const float inv1 = 1.f / lacc1;

    const int b = bh >> 4, h = bh & 15;
#pragma unroll
    for (int nt4 = 0; nt4 < 4; nt4++) {
#pragma unroll
        for (int i2 = 0; i2 < 4; i2++) {
            const int i = 2 * i2;
            const int qg   = qglow + ((i & 2) ? 8 : 0);
            const float inv = (i & 2) ? inv1 : inv0;
            const int colb = nt4 * 16 + (lane & 3) * 2 + ((i & 4) ? 8 : 0);
            const float v0 = oacc[nt4].x[i]     * inv;
            const float v1 = oacc[nt4].x[i + 1] * inv;
            __half h0, l0, h1, l1;
            fp16_split(v0, h0, l0); fp16_split(v1, h1, l1);
            __half2 hh; hh.x = h0; hh.y = h1;
            __half2 ll; ll.x = l0; ll.y = l1;
            const size_t o = ((size_t)(b * kSeq + qg)) * kEmbed + h * kHeadDim + colb;
            *(__half2*)(g_ath + o) = hh;
            *(__half2*)(g_atl + o) = ll;
        }
    }
}

// ======================= launch =======================
extern "C" void kernel_launch(void* const* d_in, const int* in_sizes, int n_in,
                              void* d_out, int out_size) {
    const float* x  = (const float*)d_in[0];
    const float* Wq = (const float*)d_in[1];
    const float* Wk = (const float*)d_in[2];
    const float* Wv = (const float*)d_in[3];
    const float* bq = (const float*)d_in[4];
    const float* bk = (const float*)d_in[5];
    const float* bv = (const float*)d_in[6];
    const float* Wp = (const float*)d_in[7];
    const float* bp = (const float*)d_in[8];
    float* out = (float*)d_out;

    cudaFuncSetAttribute(gemm_wmma_kernel, cudaFuncAttributeMaxDynamicSharedMemorySize, kGemmSmem);
    cudaFuncSetAttribute(attn_wmma_kernel, cudaFuncAttributeMaxDynamicSharedMemorySize, kAttnSmem);

    convert_x_kernel<<<(kRows * kEmbed + 255) / 256, 256>>>(x);
    pack_qkv_kernel<<<(kEmbed * kQkvN + 255) / 256, 256>>>(Wq, Wk, Wv, bq, bk, bv);
    pack_wp_kernel<<<(kEmbed * kEmbed + 255) / 256, 256>>>(Wp);

    // QKV projection: [8192,1024] x [1024,3072] -> fp16 q(split)/k/v
    gemm_wmma_kernel<<<dim3(kQkvN / 128, kRows / 64), 256, kGemmSmem>>>(nullptr, nullptr, 0);

    // causal attention on tensor cores (fp16 asymmetric split)
    attn_wmma_kernel<<<dim3(kSeq / 128, kBatch * kHeads), 256, kAttnSmem>>>();

    // output projection: [8192,1024] x [1024,1024] + bias
    gemm_wmma_kernel<<<dim3(kEmbed / 128, kRows / 64), 256, kGemmSmem>>>(bp, out, 1);
}

// round 11
// speedup vs baseline: 3.5089x; 1.5497x over previous
#include <cuda_runtime.h>
#include <cuda_bf16.h>
#include <cuda_fp16.h>
#include <cuda_pipeline.h>
#include <mma.h>
#include <math.h>

using namespace nvcuda;

constexpr int kEmbed   = 1024;
constexpr int kHeads   = 16;
constexpr int kHeadDim = 64;
constexpr int kSeq     = 2048;
constexpr int kBatch   = 4;
constexpr int kQkvN    = 3 * kEmbed;          // 3072
constexpr int kRows    = kBatch * kSeq;       // 8192
constexpr int kBHT     = kBatch * kHeads * kSeq * kHeadDim;

// -------- scratch (static device globals; no runtime allocation) --------
__device__ __align__(128) __half g_x[kRows * kEmbed];      // x single fp16
__device__ __align__(128) __half g_wqkv[kEmbed * kQkvN];   // weights single fp16
__device__ __align__(128) float g_bqkv[kQkvN];
// attention operands: q split-2 (pre-scaled by 0.125), k/v single fp16
__device__ __align__(128) __half g_qh2[kBHT];
__device__ __align__(128) __half g_ql2[kBHT];
__device__ __align__(128) __half g_kh2[kBHT];
__device__ __align__(128) __half g_vh2[kBHT];
__device__ __align__(128) __half g_at[kRows * kEmbed];     // att single fp16
__device__ __align__(128) __half g_wp[kEmbed * kEmbed];    // single fp16

// ======================= conversion / packing =======================
__device__ __forceinline__ void fp16_split(float v, __half& hi, __half& lo) {
    hi = __float2half(v);
    lo = __float2half(v - __half2float(hi));
}

__global__ void convert_x_kernel(const float* __restrict__ x) {
    int idx = blockIdx.x * blockDim.x + threadIdx.x;
    if (idx < kRows * kEmbed) g_x[idx] = __float2half(x[idx]);
}

__global__ void pack_qkv_kernel(const float* __restrict__ Wq, const float* __restrict__ Wk,
                                const float* __restrict__ Wv, const float* __restrict__ bq,
                                const float* __restrict__ bk, const float* __restrict__ bv) {
    int idx = blockIdx.x * blockDim.x + threadIdx.x;
    if (idx < kEmbed * kQkvN) {
        int e = idx / kQkvN;
        int n = idx % kQkvN;
        int which = n >> 10;
        int hd    = n & 1023;
        int h = hd >> 6, d = hd & 63;
        const float* W = (which == 0) ? Wq : (which == 1) ? Wk : Wv;
        g_wqkv[idx] = __float2half(W[((size_t)h * kEmbed + e) * kHeadDim + d]);
    }
    if (idx < kQkvN) {
        int which = idx >> 10;
        int hd    = idx & 1023;
        const float* bb = (which == 0) ? bq : (which == 1) ? bk : bv;
        g_bqkv[idx] = bb[hd];
    }
}

__global__ void pack_wp_kernel(const float* __restrict__ Wp) {
    int idx = blockIdx.x * blockDim.x + threadIdx.x;
    if (idx < kEmbed * kEmbed) g_wp[idx] = __float2half(Wp[idx]);
}

// ======================= fp16 WMMA GEMM =======================
// acc += A*B (both single fp16, fp32 accumulate). Block 64x128, BK=32,
// cp.async 3-stage, 256 threads / 8 warps (2m x 4n), warp tile 32x32, 3 CTAs/SM.
constexpr int kGA = 0;                       // [64][40] half = 5120
constexpr int kGB = 5120;                    // [32][136] half = 8704
constexpr int kGStage = 13824;
constexpr int kGemmSmem = 3 * kGStage;       // 41472

__global__ __launch_bounds__(256, 3)
void gemm_wmma_kernel(const float* __restrict__ bias_arg, float* __restrict__ outp, int mode) {
    extern __shared__ char sm[];

    const int N = (mode == 0) ? kQkvN : kEmbed;
    const __half* A = (mode == 0) ? g_x : g_at;
    const __half* B = (mode == 0) ? g_wqkv : g_wp;
    const float* bias = (mode == 0) ? g_bqkv : bias_arg;

    const int tid  = threadIdx.x;
    const int warp = tid >> 5, lane = tid & 31;
    const int wm   = warp >> 2, wn = warp & 3;   // 2 x 4 warp grid
    const int bm   = blockIdx.y * 64;
    const int bn   = blockIdx.x * 128;

    const int ar = tid >> 2,  ac = (tid & 3) * 8;    // A: 64 rows x 32 cols
    const int br = tid >> 4,  bc = (tid & 15) * 8;   // B: 32 rows x 128 cols

    auto loadStage = [&](int kt, int s) {
        const int k0 = kt * 32;
        char* st = sm + s * kGStage;
        __half* sA = (__half*)(st + kGA);
        __half* sB = (__half*)(st + kGB);
        const size_t asrc = (size_t)(bm + ar) * kEmbed + k0 + ac;
        __pipeline_memcpy_async(sA + ar * 40 + ac, A + asrc, 16);
        const size_t bsrc = (size_t)(k0 + br) * N + bn + bc;
        __pipeline_memcpy_async(sB + br * 136 + bc, B + bsrc, 16);
        const size_t bsrc2 = bsrc + (size_t)16 * N;
        __pipeline_memcpy_async(sB + (br + 16) * 136 + bc, B + bsrc2, 16);
        __pipeline_commit();
    };

    wmma::fragment<wmma::accumulator, 16, 16, 16, float> acc[2][2];
#pragma unroll
    for (int mi = 0; mi < 2; mi++)
#pragma unroll
        for (int ni = 0; ni < 2; ni++) wmma::fill_fragment(acc[mi][ni], 0.0f);

    constexpr int NT = kEmbed / 32;
    loadStage(0, 0);
    loadStage(1, 1);

    for (int kt = 0; kt < NT; kt++) {
        if (kt < NT - 2) __pipeline_wait_prior(1);
        else             __pipeline_wait_prior(0);
        __syncthreads();
        if (kt + 2 < NT) loadStage(kt + 2, (kt + 2) % 3);

        char* st = sm + (kt % 3) * kGStage;
        const __half* sA = (const __half*)(st + kGA);
        const __half* sB = (const __half*)(st + kGB);

#pragma unroll
        for (int kk = 0; kk < 2; kk++) {
            wmma::fragment<wmma::matrix_a, 16, 16, 16, __half, wmma::row_major> fa[2];
            wmma::fragment<wmma::matrix_b, 16, 16, 16, __half, wmma::row_major> fb[2];
#pragma unroll
            for (int mi = 0; mi < 2; mi++)
                wmma::load_matrix_sync(fa[mi], sA + (wm * 32 + mi * 16) * 40 + kk * 16, 40);
#pragma unroll
            for (int ni = 0; ni < 2; ni++)
                wmma::load_matrix_sync(fb[ni], sB + (kk * 16) * 136 + wn * 32 + ni * 16, 136);
#pragma unroll
            for (int mi = 0; mi < 2; mi++)
#pragma unroll
                for (int ni = 0; ni < 2; ni++)
                    wmma::mma_sync(acc[mi][ni], fa[mi], fb[ni], acc[mi][ni]);
        }
    }

    // direct fragment epilogue (sm_80+ accumulator layout)
#pragma unroll
    for (int mi = 0; mi < 2; mi++) {
#pragma unroll
        for (int ni = 0; ni < 2; ni++) {
#pragma unroll
            for (int i2 = 0; i2 < 4; i2++) {
                const int i = 2 * i2;
                const int row = bm + wm * 32 + mi * 16 + (lane >> 2) + ((i & 2) ? 8 : 0);
                const int col = bn + wn * 32 + ni * 16 + (lane & 3) * 2 + ((i & 4) ? 8 : 0);
                float v0 = acc[mi][ni].x[i]     + bias[col];
                float v1 = acc[mi][ni].x[i + 1] + bias[col + 1];
                if (mode == 0) {
                    const int which = col >> 10, hd = col & 1023;
                    const int h = hd >> 6, d = hd & 63;
                    const int b = row >> 11, t = row & 2047;
                    const size_t o = (((size_t)(b * kHeads + h) * kSeq) + t) * kHeadDim + d;
                    if (which == 0) {
                        v0 *= 0.125f; v1 *= 0.125f;
                        __half h0, l0, h1, l1;
                        fp16_split(v0, h0, l0); fp16_split(v1, h1, l1);
                        __half2 hh; hh.x = h0; hh.y = h1;
                        __half2 ll; ll.x = l0; ll.y = l1;
                        *(__half2*)(g_qh2 + o) = hh;
                        *(__half2*)(g_ql2 + o) = ll;
                    } else {
                        __half2 hh; hh.x = __float2half(v0); hh.y = __float2half(v1);
                        __half* dst = (which == 1) ? g_kh2 : g_vh2;
                        *(__half2*)(dst + o) = hh;
                    }
                } else {
                    float2 vv; vv.x = v0; vv.y = v1;
                    *(float2*)(outp + (size_t)row * kEmbed + col) = vv;
                }
            }
        }
    }
}

// ======================= fp16 WMMA causal attention =======================
// 256 threads, 128 q-rows/CTA, kv tile 64, cp.async double buffer.
// S = (qh+ql)*kh (2 MMAs), O += p*vh (1 MMA, single-fp16 P). Register softmax.
constexpr int kKVBuf  = 2 * 9216;            // kh, vh each half[64][72]
constexpr int kAPH    = 2 * kKVBuf;          // 36864, half[128][72]
constexpr int kAttnSmem = kAPH + 18432;      // 55296

__global__ __launch_bounds__(256)
void attn_wmma_kernel() {
    extern __shared__ char sm[];
    __half* ph = (__half*)(sm + kAPH);

    const int qi  = gridDim.x - 1 - blockIdx.x;   // big tiles first
    const int bh  = blockIdx.y;
    const int tid = threadIdx.x;
    const int warp = tid >> 5, lane = tid & 31;
    const int q0  = qi * 128;
    const size_t base = (size_t)bh * kSeq * kHeadDim;

    auto loadKV = [&](int kt, int b) {
        const int k0 = kt * 64;
        char* kv = sm + b * kKVBuf;
        __half* skh = (__half*)(kv);
        __half* svh = (__half*)(kv + 9216);
#pragma unroll
        for (int i = 0; i < 2; i++) {
            const int idx = i * 256 + tid;
            const int r = idx >> 3, c8 = (idx & 7) * 8;
            const size_t g = base + (size_t)(k0 + r) * kHeadDim + c8;
            const int so = r * 72 + c8;
            __pipeline_memcpy_async(skh + so, g_kh2 + g, 16);
            __pipeline_memcpy_async(svh + so, g_vh2 + g, 16);
        }
        __pipeline_commit();
    };

    wmma::fragment<wmma::matrix_a, 16, 16, 16, __half, wmma::row_major> fqh[4], fql[4];
#pragma unroll
    for (int kk = 0; kk < 4; kk++) {
        const size_t qo = base + (size_t)(q0 + warp * 16) * kHeadDim + kk * 16;
        wmma::load_matrix_sync(fqh[kk], g_qh2 + qo, kHeadDim);
        wmma::load_matrix_sync(fql[kk], g_ql2 + qo, kHeadDim);
    }

    wmma::fragment<wmma::accumulator, 16, 16, 16, float> oacc[4];
#pragma unroll
    for (int nt4 = 0; nt4 < 4; nt4++) wmma::fill_fragment(oacc[nt4], 0.0f);

    const int rlow  = warp * 16 + (lane >> 2);
    const int qglow = q0 + rlow;
    float lacc0 = 0.f, lacc1 = 0.f;

    const int ntiles = 2 * qi + 2;
    loadKV(0, 0);

    for (int kt = 0; kt < ntiles; kt++) {
        const int k0  = kt * 64;
        const int buf = kt & 1;
        char* kv = sm + buf * kKVBuf;
        const __half* skh = (const __half*)(kv);
        const __half* svh = (const __half*)(kv + 9216);

        __pipeline_wait_prior(0);
        __syncthreads();
        if (kt + 1 < ntiles) loadKV(kt + 1, buf ^ 1);

        // S = Q K^T, softmax in registers, P -> smem single fp16
#pragma unroll
        for (int nt4 = 0; nt4 < 4; nt4++) {
            wmma::fragment<wmma::accumulator, 16, 16, 16, float> sacc;
            wmma::fill_fragment(sacc, 0.0f);
#pragma unroll
            for (int kk = 0; kk < 4; kk++) {
                wmma::fragment<wmma::matrix_b, 16, 16, 16, __half, wmma::col_major> fbh;
                wmma::load_matrix_sync(fbh, skh + (nt4 * 16) * 72 + kk * 16, 72);
                wmma::mma_sync(sacc, fqh[kk], fbh, sacc);
                wmma::mma_sync(sacc, fql[kk], fbh, sacc);
            }
#pragma unroll
            for (int i2 = 0; i2 < 4; i2++) {
                const int i = 2 * i2;
                const int rl   = rlow + ((i & 2) ? 8 : 0);
                const int qg   = qglow + ((i & 2) ? 8 : 0);
                const int colb = nt4 * 16 + (lane & 3) * 2 + ((i & 4) ? 8 : 0);
                const int kg   = k0 + colb;
                const float p0 = (kg     <= qg) ? __expf(sacc.x[i])     : 0.f;
                const float p1 = (kg + 1 <= qg) ? __expf(sacc.x[i + 1]) : 0.f;
                const __half h0 = __float2half(p0);
                const __half h1 = __float2half(p1);
                // sum the ROUNDED p so the normalizer matches the MMA input
                const float q0f = __half2float(h0), q1f = __half2float(h1);
                if (i & 2) lacc1 += q0f + q1f; else lacc0 += q0f + q1f;
                __half2 hh; hh.x = h0; hh.y = h1;
                *(__half2*)(ph + rl * 72 + colb) = hh;
            }
        }
        __syncwarp();

        // O += P V
#pragma unroll
        for (int kk = 0; kk < 4; kk++) {
            wmma::fragment<wmma::matrix_a, 16, 16, 16, __half, wmma::row_major> fph;
            wmma::load_matrix_sync(fph, ph + (warp * 16) * 72 + kk * 16, 72);
#pragma unroll
            for (int nt4 = 0; nt4 < 4; nt4++) {
                wmma::fragment<wmma::matrix_b, 16, 16, 16, __half, wmma::row_major> fvh;
                wmma::load_matrix_sync(fvh, svh + (kk * 16) * 72 + nt4 * 16, 72);
                wmma::mma_sync(oacc[nt4], fph, fvh, oacc[nt4]);
            }
        }
    }

    lacc0 += __shfl_xor_sync(0xffffffffu, lacc0, 1);
    lacc0 += __shfl_xor_sync(0xffffffffu, lacc0, 2);
    lacc1 += __shfl_xor_sync(0xffffffffu, lacc1, 1);
    lacc1 += __shfl_xor_sync(0xffffffffu, lacc1, 2);
    const float inv0 = 1.f / lacc0;
    const float inv1 = 1.f / lacc1;

    const int b = bh >> 4, h = bh & 15;
#pragma unroll
    for (int nt4 = 0; nt4 < 4; nt4++) {
#pragma unroll
        for (int i2 = 0; i2 < 4; i2++) {
            const int i = 2 * i2;
            const int qg   = qglow + ((i & 2) ? 8 : 0);
            const float inv = (i & 2) ? inv1 : inv0;
            const int colb = nt4 * 16 + (lane & 3) * 2 + ((i & 4) ? 8 : 0);
            const float v0 = oacc[nt4].x[i]     * inv;
            const float v1 = oacc[nt4].x[i + 1] * inv;
            __half2 hh; hh.x = __float2half(v0); hh.y = __float2half(v1);
            const size_t o = ((size_t)(b * kSeq + qg)) * kEmbed + h * kHeadDim + colb;
            *(__half2*)(g_at + o) = hh;
        }
    }
}

// ======================= launch =======================
extern "C" void kernel_launch(void* const* d_in, const int* in_sizes, int n_in,
                              void* d_out, int out_size) {
    const float* x  = (const float*)d_in[0];
    const float* Wq = (const float*)d_in[1];
    const float* Wk = (const float*)d_in[2];
    const float* Wv = (const float*)d_in[3];
    const float* bq = (const float*)d_in[4];
    const float* bk = (const float*)d_in[5];
    const float* bv = (const float*)d_in[6];
    const float* Wp = (const float*)d_in[7];
    const float* bp = (const float*)d_in[8];
    float* out = (float*)d_out;

    cudaFuncSetAttribute(gemm_wmma_kernel, cudaFuncAttributeMaxDynamicSharedMemorySize, kGemmSmem);
    cudaFuncSetAttribute(attn_wmma_kernel, cudaFuncAttributeMaxDynamicSharedMemorySize, kAttnSmem);

    convert_x_kernel<<<(kRows * kEmbed + 255) / 256, 256>>>(x);
    pack_qkv_kernel<<<(kEmbed * kQkvN + 255) / 256, 256>>>(Wq, Wk, Wv, bq, bk, bv);
    pack_wp_kernel<<<(kEmbed * kEmbed + 255) / 256, 256>>>(Wp);

    // QKV projection: [8192,1024] x [1024,3072] -> fp16 q(split)/k/v
    gemm_wmma_kernel<<<dim3(kQkvN / 128, kRows / 64), 256, kGemmSmem>>>(nullptr, nullptr, 0);

    // causal attention on tensor cores
    attn_wmma_kernel<<<dim3(kSeq / 128, kBatch * kHeads), 256, kAttnSmem>>>();

    // output projection: [8192,1024] x [1024,1024] + bias
    gemm_wmma_kernel<<<dim3(kEmbed / 128, kRows / 64), 256, kGemmSmem>>>(bp, out, 1);
}

// round 12
// speedup vs baseline: 3.7521x; 1.0693x over previous
#include <cuda_runtime.h>
#include <cuda_bf16.h>
#include <cuda_fp16.h>
#include <cuda_pipeline.h>
#include <mma.h>
#include <math.h>

using namespace nvcuda;

constexpr int kEmbed   = 1024;
constexpr int kHeads   = 16;
constexpr int kHeadDim = 64;
constexpr int kSeq     = 2048;
constexpr int kBatch   = 4;
constexpr int kQkvN    = 3 * kEmbed;          // 3072
constexpr int kRows    = kBatch * kSeq;       // 8192
constexpr int kBHT     = kBatch * kHeads * kSeq * kHeadDim;

// -------- scratch (static device globals; no runtime allocation) --------
__device__ __align__(128) __half g_x[kRows * kEmbed];      // x single fp16
__device__ __align__(128) __half g_wqkv[kEmbed * kQkvN];   // weights single fp16
__device__ __align__(128) float g_bqkv[kQkvN];
// attention operands, all single fp16 (q pre-scaled by 0.125)
__device__ __align__(128) __half g_q[kBHT];
__device__ __align__(128) __half g_k[kBHT];
__device__ __align__(128) __half g_v[kBHT];
__device__ __align__(128) __half g_at[kRows * kEmbed];     // att single fp16
__device__ __align__(128) __half g_wp[kEmbed * kEmbed];    // single fp16

// ======================= conversion / packing =======================
__global__ void convert_x_kernel(const float* __restrict__ x) {
    int idx = blockIdx.x * blockDim.x + threadIdx.x;
    if (idx < kRows * kEmbed) g_x[idx] = __float2half(x[idx]);
}

__global__ void pack_qkv_kernel(const float* __restrict__ Wq, const float* __restrict__ Wk,
                                const float* __restrict__ Wv, const float* __restrict__ bq,
                                const float* __restrict__ bk, const float* __restrict__ bv) {
    int idx = blockIdx.x * blockDim.x + threadIdx.x;
    if (idx < kEmbed * kQkvN) {
        int e = idx / kQkvN;
        int n = idx % kQkvN;
        int which = n >> 10;
        int hd    = n & 1023;
        int h = hd >> 6, d = hd & 63;
        const float* W = (which == 0) ? Wq : (which == 1) ? Wk : Wv;
        g_wqkv[idx] = __float2half(W[((size_t)h * kEmbed + e) * kHeadDim + d]);
    }
    if (idx < kQkvN) {
        int which = idx >> 10;
        int hd    = idx & 1023;
        const float* bb = (which == 0) ? bq : (which == 1) ? bk : bv;
        g_bqkv[idx] = bb[hd];
    }
}

__global__ void pack_wp_kernel(const float* __restrict__ Wp) {
    int idx = blockIdx.x * blockDim.x + threadIdx.x;
    if (idx < kEmbed * kEmbed) g_wp[idx] = __float2half(Wp[idx]);
}

// ======================= fp16 WMMA GEMM =======================
// acc += A*B (single fp16, fp32 accumulate). Block 128x128, BK=32,
// cp.async 3-stage, 256 threads / 8 warps (2m x 4n), warp tile 64x32.
constexpr int kGA = 0;                       // [128][40] half = 10240
constexpr int kGB = 10240;                   // [32][136] half = 8704
constexpr int kGStage = 18944;
constexpr int kGemmSmem = 3 * kGStage;       // 56832 -> 2 CTAs/SM

__global__ __launch_bounds__(256, 2)
void gemm_wmma_kernel(const float* __restrict__ bias_arg, float* __restrict__ outp, int mode) {
    extern __shared__ char sm[];

    const int N = (mode == 0) ? kQkvN : kEmbed;
    const __half* A = (mode == 0) ? g_x : g_at;
    const __half* B = (mode == 0) ? g_wqkv : g_wp;
    const float* bias = (mode == 0) ? g_bqkv : bias_arg;

    const int tid  = threadIdx.x;
    const int warp = tid >> 5, lane = tid & 31;
    const int wm   = warp >> 2, wn = warp & 3;   // 2 x 4 warp grid
    const int bm   = blockIdx.y * 128;
    const int bn   = blockIdx.x * 128;

    auto loadStage = [&](int kt, int s) {
        const int k0 = kt * 32;
        char* st = sm + s * kGStage;
        __half* sA = (__half*)(st + kGA);
        __half* sB = (__half*)(st + kGB);
#pragma unroll
        for (int i = 0; i < 2; i++) {
            const int idx = i * 256 + tid;
            const int ar = idx >> 2, ac = (idx & 3) * 8;
            const size_t asrc = (size_t)(bm + ar) * kEmbed + k0 + ac;
            __pipeline_memcpy_async(sA + ar * 40 + ac, A + asrc, 16);
            const int br = idx >> 4, bc = (idx & 15) * 8;
            const size_t bsrc = (size_t)(k0 + br) * N + bn + bc;
            __pipeline_memcpy_async(sB + br * 136 + bc, B + bsrc, 16);
        }
        __pipeline_commit();
    };

    wmma::fragment<wmma::accumulator, 16, 16, 16, float> acc[4][2];
#pragma unroll
    for (int mi = 0; mi < 4; mi++)
#pragma unroll
        for (int ni = 0; ni < 2; ni++) wmma::fill_fragment(acc[mi][ni], 0.0f);

    constexpr int NT = kEmbed / 32;
    loadStage(0, 0);
    loadStage(1, 1);

    for (int kt = 0; kt < NT; kt++) {
        if (kt < NT - 2) __pipeline_wait_prior(1);
        else             __pipeline_wait_prior(0);
        __syncthreads();
        if (kt + 2 < NT) loadStage(kt + 2, (kt + 2) % 3);

        char* st = sm + (kt % 3) * kGStage;
        const __half* sA = (const __half*)(st + kGA);
        const __half* sB = (const __half*)(st + kGB);

#pragma unroll
        for (int kk = 0; kk < 2; kk++) {
            wmma::fragment<wmma::matrix_a, 16, 16, 16, __half, wmma::row_major> fa[4];
            wmma::fragment<wmma::matrix_b, 16, 16, 16, __half, wmma::row_major> fb[2];
#pragma unroll
            for (int mi = 0; mi < 4; mi++)
                wmma::load_matrix_sync(fa[mi], sA + (wm * 64 + mi * 16) * 40 + kk * 16, 40);
#pragma unroll
            for (int ni = 0; ni < 2; ni++)
                wmma::load_matrix_sync(fb[ni], sB + (kk * 16) * 136 + wn * 32 + ni * 16, 136);
#pragma unroll
            for (int mi = 0; mi < 4; mi++)
#pragma unroll
                for (int ni = 0; ni < 2; ni++)
                    wmma::mma_sync(acc[mi][ni], fa[mi], fb[ni], acc[mi][ni]);
        }
    }

    // direct fragment epilogue (sm_80+ accumulator layout)
#pragma unroll
    for (int mi = 0; mi < 4; mi++) {
#pragma unroll
        for (int ni = 0; ni < 2; ni++) {
#pragma unroll
            for (int i2 = 0; i2 < 4; i2++) {
                const int i = 2 * i2;
                const int row = bm + wm * 64 + mi * 16 + (lane >> 2) + ((i & 2) ? 8 : 0);
                const int col = bn + wn * 32 + ni * 16 + (lane & 3) * 2 + ((i & 4) ? 8 : 0);
                float v0 = acc[mi][ni].x[i]     + bias[col];
                float v1 = acc[mi][ni].x[i + 1] + bias[col + 1];
                if (mode == 0) {
                    const int which = col >> 10, hd = col & 1023;
                    const int h = hd >> 6, d = hd & 63;
                    const int b = row >> 11, t = row & 2047;
                    const size_t o = (((size_t)(b * kHeads + h) * kSeq) + t) * kHeadDim + d;
                    if (which == 0) { v0 *= 0.125f; v1 *= 0.125f; }
                    __half* dst = (which == 0) ? g_q : ((which == 1) ? g_k : g_v);
                    __half2 hh; hh.x = __float2half(v0); hh.y = __float2half(v1);
                    *(__half2*)(dst + o) = hh;
                } else {
                    float2 vv; vv.x = v0; vv.y = v1;
                    *(float2*)(outp + (size_t)row * kEmbed + col) = vv;
                }
            }
        }
    }
}

// ======================= fp16 WMMA causal attention =======================
// 256 threads, 128 q-rows/CTA, kv tile 64, cp.async double buffer.
// S = q*k (1 MMA), O += p*v (1 MMA). Register softmax, all single fp16.
constexpr int kKVBuf  = 2 * 9216;            // k, v each half[64][72]
constexpr int kAPH    = 2 * kKVBuf;          // 36864, half[128][72]
constexpr int kAttnSmem = kAPH + 18432;      // 55296

__global__ __launch_bounds__(256)
void attn_wmma_kernel() {
    extern __shared__ char sm[];
    __half* ph = (__half*)(sm + kAPH);

    const int qi  = gridDim.x - 1 - blockIdx.x;   // big tiles first
    const int bh  = blockIdx.y;
    const int tid = threadIdx.x;
    const int warp = tid >> 5, lane = tid & 31;
    const int q0  = qi * 128;
    const size_t base = (size_t)bh * kSeq * kHeadDim;

    auto loadKV = [&](int kt, int b) {
        const int k0 = kt * 64;
        char* kv = sm + b * kKVBuf;
        __half* skh = (__half*)(kv);
        __half* svh = (__half*)(kv + 9216);
#pragma unroll
        for (int i = 0; i < 2; i++) {
            const int idx = i * 256 + tid;
            const int r = idx >> 3, c8 = (idx & 7) * 8;
            const size_t g = base + (size_t)(k0 + r) * kHeadDim + c8;
            const int so = r * 72 + c8;
            __pipeline_memcpy_async(skh + so, g_k + g, 16);
            __pipeline_memcpy_async(svh + so, g_v + g, 16);
        }
        __pipeline_commit();
    };

    wmma::fragment<wmma::matrix_a, 16, 16, 16, __half, wmma::row_major> fq[4];
#pragma unroll
    for (int kk = 0; kk < 4; kk++) {
        const size_t qo = base + (size_t)(q0 + warp * 16) * kHeadDim + kk * 16;
        wmma::load_matrix_sync(fq[kk], g_q + qo, kHeadDim);
    }

    wmma::fragment<wmma::accumulator, 16, 16, 16, float> oacc[4];
#pragma unroll
    for (int nt4 = 0; nt4 < 4; nt4++) wmma::fill_fragment(oacc[nt4], 0.0f);

    const int rlow  = warp * 16 + (lane >> 2);
    const int qglow = q0 + rlow;
    float lacc0 = 0.f, lacc1 = 0.f;

    const int ntiles = 2 * qi + 2;
    loadKV(0, 0);

    for (int kt = 0; kt < ntiles; kt++) {
        const int k0  = kt * 64;
        const int buf = kt & 1;
        char* kv = sm + buf * kKVBuf;
        const __half* skh = (const __half*)(kv);
        const __half* svh = (const __half*)(kv + 9216);

        __pipeline_wait_prior(0);
        __syncthreads();
        if (kt + 1 < ntiles) loadKV(kt + 1, buf ^ 1);

        // S = Q K^T, softmax in registers, P -> smem single fp16
#pragma unroll
        for (int nt4 = 0; nt4 < 4; nt4++) {
            wmma::fragment<wmma::accumulator, 16, 16, 16, float> sacc;
            wmma::fill_fragment(sacc, 0.0f);
#pragma unroll
            for (int kk = 0; kk < 4; kk++) {
                wmma::fragment<wmma::matrix_b, 16, 16, 16, __half, wmma::col_major> fbh;
                wmma::load_matrix_sync(fbh, skh + (nt4 * 16) * 72 + kk * 16, 72);
                wmma::mma_sync(sacc, fq[kk], fbh, sacc);
            }
#pragma unroll
            for (int i2 = 0; i2 < 4; i2++) {
                const int i = 2 * i2;
                const int rl   = rlow + ((i & 2) ? 8 : 0);
                const int qg   = qglow + ((i & 2) ? 8 : 0);
                const int colb = nt4 * 16 + (lane & 3) * 2 + ((i & 4) ? 8 : 0);
                const int kg   = k0 + colb;
                const float p0 = (kg     <= qg) ? __expf(sacc.x[i])     : 0.f;
                const float p1 = (kg + 1 <= qg) ? __expf(sacc.x[i + 1]) : 0.f;
                const __half h0 = __float2half(p0);
                const __half h1 = __float2half(p1);
                // sum the ROUNDED p so the normalizer matches the MMA input
                const float q0f = __half2float(h0), q1f = __half2float(h1);
                if (i & 2) lacc1 += q0f + q1f; else lacc0 += q0f + q1f;
                __half2 hh; hh.x = h0; hh.y = h1;
                *(__half2*)(ph + rl * 72 + colb) = hh;
            }
        }
        __syncwarp();

        // O += P V
#pragma unroll
        for (int kk = 0; kk < 4; kk++) {
            wmma::fragment<wmma::matrix_a, 16, 16, 16, __half, wmma::row_major> fph;
            wmma::load_matrix_sync(fph, ph + (warp * 16) * 72 + kk * 16, 72);
#pragma unroll
            for (int nt4 = 0; nt4 < 4; nt4++) {
                wmma::fragment<wmma::matrix_b, 16, 16, 16, __half, wmma::row_major> fvh;
                wmma::load_matrix_sync(fvh, svh + (kk * 16) * 72 + nt4 * 16, 72);
                wmma::mma_sync(oacc[nt4], fph, fvh, oacc[nt4]);
            }
        }
    }

    lacc0 += __shfl_xor_sync(0xffffffffu, lacc0, 1);
    lacc0 += __shfl_xor_sync(0xffffffffu, lacc0, 2);
    lacc1 += __shfl_xor_sync(0xffffffffu, lacc1, 1);
    lacc1 += __shfl_xor_sync(0xffffffffu, lacc1, 2);
    const float inv0 = 1.f / lacc0;
    const float inv1 = 1.f / lacc1;

    const int b = bh >> 4, h = bh & 15;
#pragma unroll
    for (int nt4 = 0; nt4 < 4; nt4++) {
#pragma unroll
        for (int i2 = 0; i2 < 4; i2++) {
            const int i = 2 * i2;
            const int qg   = qglow + ((i & 2) ? 8 : 0);
            const float inv = (i & 2) ? inv1 : inv0;
            const int colb = nt4 * 16 + (lane & 3) * 2 + ((i & 4) ? 8 : 0);
            const float v0 = oacc[nt4].x[i]     * inv;
            const float v1 = oacc[nt4].x[i + 1] * inv;
            __half2 hh; hh.x = __float2half(v0); hh.y = __float2half(v1);
            const size_t o = ((size_t)(b * kSeq + qg)) * kEmbed + h * kHeadDim + colb;
            *(__half2*)(g_at + o) = hh;
        }
    }
}

// ======================= launch =======================
extern "C" void kernel_launch(void* const* d_in, const int* in_sizes, int n_in,
                              void* d_out, int out_size) {
    const float* x  = (const float*)d_in[0];
    const float* Wq = (const float*)d_in[1];
    const float* Wk = (const float*)d_in[2];
    const float* Wv = (const float*)d_in[3];
    const float* bq = (const float*)d_in[4];
    const float* bk = (const float*)d_in[5];
    const float* bv = (const float*)d_in[6];
    const float* Wp = (const float*)d_in[7];
    const float* bp = (const float*)d_in[8];
    float* out = (float*)d_out;

    cudaFuncSetAttribute(gemm_wmma_kernel, cudaFuncAttributeMaxDynamicSharedMemorySize, kGemmSmem);
    cudaFuncSetAttribute(attn_wmma_kernel, cudaFuncAttributeMaxDynamicSharedMemorySize, kAttnSmem);

    convert_x_kernel<<<(kRows * kEmbed + 255) / 256, 256>>>(x);
    pack_qkv_kernel<<<(kEmbed * kQkvN + 255) / 256, 256>>>(Wq, Wk, Wv, bq, bk, bv);
    pack_wp_kernel<<<(kEmbed * kEmbed + 255) / 256, 256>>>(Wp);

    // QKV projection: [8192,1024] x [1024,3072] -> fp16 q/k/v
    gemm_wmma_kernel<<<dim3(kQkvN / 128, kRows / 128), 256, kGemmSmem>>>(nullptr, nullptr, 0);

    // causal attention on tensor cores
    attn_wmma_kernel<<<dim3(kSeq / 128, kBatch * kHeads), 256, kAttnSmem>>>();

    // output projection: [8192,1024] x [1024,1024] + bias
    gemm_wmma_kernel<<<dim3(kEmbed / 128, kRows / 128), 256, kGemmSmem>>>(bp, out, 1);
}

// round 13
// speedup vs baseline: 4.2997x; 1.1460x over previous
#include <cuda_runtime.h>
#include <cuda_bf16.h>
#include <cuda_fp16.h>
#include <cuda_pipeline.h>
#include <mma.h>
#include <math.h>

using namespace nvcuda;

constexpr int kEmbed   = 1024;
constexpr int kHeads   = 16;
constexpr int kHeadDim = 64;
constexpr int kSeq     = 2048;
constexpr int kBatch   = 4;
constexpr int kQkvN    = 3 * kEmbed;          // 3072
constexpr int kRows    = kBatch * kSeq;       // 8192
constexpr int kBHT     = kBatch * kHeads * kSeq * kHeadDim;

// q pre-scale: 1/sqrt(64) * log2(e)  (exp(s/8) == exp2(s*kQScale/..): folded)
constexpr float kQScale = 0.125f * 1.4426950408889634f;

// -------- scratch (static device globals; no runtime allocation) --------
__device__ __align__(128) __half g_x[kRows * kEmbed];      // x single fp16
__device__ __align__(128) __half g_wqkv[kEmbed * kQkvN];   // weights single fp16
__device__ __align__(128) float g_bqkv[kQkvN];
// attention operands, all single fp16 (q pre-scaled by kQScale)
__device__ __align__(128) __half g_q[kBHT];
__device__ __align__(128) __half g_k[kBHT];
__device__ __align__(128) __half g_v[kBHT];
__device__ __align__(128) __half g_at[kRows * kEmbed];     // att single fp16
__device__ __align__(128) __half g_wp[kEmbed * kEmbed];    // single fp16

// ======================= conversion / packing =======================
__global__ void convert_x_kernel(const float* __restrict__ x) {
    int idx = blockIdx.x * blockDim.x + threadIdx.x;
    if (idx < kRows * kEmbed) g_x[idx] = __float2half(x[idx]);
}

__global__ void pack_qkv_kernel(const float* __restrict__ Wq, const float* __restrict__ Wk,
                                const float* __restrict__ Wv, const float* __restrict__ bq,
                                const float* __restrict__ bk, const float* __restrict__ bv) {
    int idx = blockIdx.x * blockDim.x + threadIdx.x;
    if (idx < kEmbed * kQkvN) {
        int e = idx / kQkvN;
        int n = idx % kQkvN;
        int which = n >> 10;
        int hd    = n & 1023;
        int h = hd >> 6, d = hd & 63;
        const float* W = (which == 0) ? Wq : (which == 1) ? Wk : Wv;
        g_wqkv[idx] = __float2half(W[((size_t)h * kEmbed + e) * kHeadDim + d]);
    }
    if (idx < kQkvN) {
        int which = idx >> 10;
        int hd    = idx & 1023;
        const float* bb = (which == 0) ? bq : (which == 1) ? bk : bv;
        g_bqkv[idx] = bb[hd];
    }
}

__global__ void pack_wp_kernel(const float* __restrict__ Wp) {
    int idx = blockIdx.x * blockDim.x + threadIdx.x;
    if (idx < kEmbed * kEmbed) g_wp[idx] = __float2half(Wp[idx]);
}

// ======================= fp16 WMMA GEMM =======================
// acc += A*B (single fp16, fp32 accumulate). Block 128x128, BK=32,
// cp.async 3-stage, 128 threads / 4 warps (2m x 2n), warp tile 64x64, 2 CTAs/SM.
constexpr int kGA = 0;                       // [128][40] half = 10240
constexpr int kGB = 10240;                   // [32][136] half = 8704
constexpr int kGStage = 18944;
constexpr int kGemmSmem = 3 * kGStage;       // 56832

__global__ __launch_bounds__(128, 2)
void gemm_wmma_kernel(const float* __restrict__ bias_arg, float* __restrict__ outp, int mode) {
    extern __shared__ char sm[];

    const int N = (mode == 0) ? kQkvN : kEmbed;
    const __half* A = (mode == 0) ? g_x : g_at;
    const __half* B = (mode == 0) ? g_wqkv : g_wp;
    const float* bias = (mode == 0) ? g_bqkv : bias_arg;

    const int tid  = threadIdx.x;
    const int warp = tid >> 5, lane = tid & 31;
    const int wm   = warp >> 1, wn = warp & 1;   // 2 x 2 warp grid
    const int bm   = blockIdx.y * 128;
    const int bn   = blockIdx.x * 128;

    auto loadStage = [&](int kt, int s) {
        const int k0 = kt * 32;
        char* st = sm + s * kGStage;
        __half* sA = (__half*)(st + kGA);
        __half* sB = (__half*)(st + kGB);
#pragma unroll
        for (int i = 0; i < 4; i++) {
            const int idx = i * 128 + tid;
            const int ar = idx >> 2, ac = (idx & 3) * 8;
            const size_t asrc = (size_t)(bm + ar) * kEmbed + k0 + ac;
            __pipeline_memcpy_async(sA + ar * 40 + ac, A + asrc, 16);
            const int br = idx >> 4, bc = (idx & 15) * 8;
            const size_t bsrc = (size_t)(k0 + br) * N + bn + bc;
            __pipeline_memcpy_async(sB + br * 136 + bc, B + bsrc, 16);
        }
        __pipeline_commit();
    };

    wmma::fragment<wmma::accumulator, 16, 16, 16, float> acc[4][4];
#pragma unroll
    for (int mi = 0; mi < 4; mi++)
#pragma unroll
        for (int ni = 0; ni < 4; ni++) wmma::fill_fragment(acc[mi][ni], 0.0f);

    constexpr int NT = kEmbed / 32;
    loadStage(0, 0);
    loadStage(1, 1);

    for (int kt = 0; kt < NT; kt++) {
        if (kt < NT - 2) __pipeline_wait_prior(1);
        else             __pipeline_wait_prior(0);
        __syncthreads();
        if (kt + 2 < NT) loadStage(kt + 2, (kt + 2) % 3);

        char* st = sm + (kt % 3) * kGStage;
        const __half* sA = (const __half*)(st + kGA);
        const __half* sB = (const __half*)(st + kGB);

#pragma unroll
        for (int kk = 0; kk < 2; kk++) {
            wmma::fragment<wmma::matrix_a, 16, 16, 16, __half, wmma::row_major> fa[4];
            wmma::fragment<wmma::matrix_b, 16, 16, 16, __half, wmma::row_major> fb[4];
#pragma unroll
            for (int mi = 0; mi < 4; mi++)
                wmma::load_matrix_sync(fa[mi], sA + (wm * 64 + mi * 16) * 40 + kk * 16, 40);
#pragma unroll
            for (int ni = 0; ni < 4; ni++)
                wmma::load_matrix_sync(fb[ni], sB + (kk * 16) * 136 + wn * 64 + ni * 16, 136);
#pragma unroll
            for (int mi = 0; mi < 4; mi++)
#pragma unroll
                for (int ni = 0; ni < 4; ni++)
                    wmma::mma_sync(acc[mi][ni], fa[mi], fb[ni], acc[mi][ni]);
        }
    }

    // direct fragment epilogue (sm_80+ accumulator layout)
#pragma unroll
    for (int mi = 0; mi < 4; mi++) {
#pragma unroll
        for (int ni = 0; ni < 4; ni++) {
#pragma unroll
            for (int i2 = 0; i2 < 4; i2++) {
                const int i = 2 * i2;
                const int row = bm + wm * 64 + mi * 16 + (lane >> 2) + ((i & 2) ? 8 : 0);
                const int col = bn + wn * 64 + ni * 16 + (lane & 3) * 2 + ((i & 4) ? 8 : 0);
                float v0 = acc[mi][ni].x[i]     + bias[col];
                float v1 = acc[mi][ni].x[i + 1] + bias[col + 1];
                if (mode == 0) {
                    const int which = col >> 10, hd = col & 1023;
                    const int h = hd >> 6, d = hd & 63;
                    const int b = row >> 11, t = row & 2047;
                    const size_t o = (((size_t)(b * kHeads + h) * kSeq) + t) * kHeadDim + d;
                    if (which == 0) { v0 *= kQScale; v1 *= kQScale; }
                    __half* dst = (which == 0) ? g_q : ((which == 1) ? g_k : g_v);
                    __half2 hh; hh.x = __float2half(v0); hh.y = __float2half(v1);
                    *(__half2*)(dst + o) = hh;
                } else {
                    float2 vv; vv.x = v0; vv.y = v1;
                    *(float2*)(outp + (size_t)row * kEmbed + col) = vv;
                }
            }
        }
    }
}

// ======================= fp16 WMMA causal attention =======================
// 256 threads, 128 q-rows/CTA, kv tile 64, cp.async double buffer.
// S = q*k (1 MMA), p = exp2(S) (scale folded into q), O += p*v (1 MMA).
constexpr int kKVBuf  = 2 * 9216;            // k, v each half[64][72]
constexpr int kAPH    = 2 * kKVBuf;          // 36864, half[128][72]
constexpr int kAttnSmem = kAPH + 18432;      // 55296

__global__ __launch_bounds__(256)
void attn_wmma_kernel() {
    extern __shared__ char sm[];
    __half* ph = (__half*)(sm + kAPH);

    const int qi  = gridDim.x - 1 - blockIdx.x;   // big tiles first
    const int bh  = blockIdx.y;
    const int tid = threadIdx.x;
    const int warp = tid >> 5, lane = tid & 31;
    const int q0  = qi * 128;
    const size_t base = (size_t)bh * kSeq * kHeadDim;

    auto loadKV = [&](int kt, int b) {
        const int k0 = kt * 64;
        char* kv = sm + b * kKVBuf;
        __half* skh = (__half*)(kv);
        __half* svh = (__half*)(kv + 9216);
#pragma unroll
        for (int i = 0; i < 2; i++) {
            const int idx = i * 256 + tid;
            const int r = idx >> 3, c8 = (idx & 7) * 8;
            const size_t g = base + (size_t)(k0 + r) * kHeadDim + c8;
            const int so = r * 72 + c8;
            __pipeline_memcpy_async(skh + so, g_k + g, 16);
            __pipeline_memcpy_async(svh + so, g_v + g, 16);
        }
        __pipeline_commit();
    };

    wmma::fragment<wmma::matrix_a, 16, 16, 16, __half, wmma::row_major> fq[4];
#pragma unroll
    for (int kk = 0; kk < 4; kk++) {
        const size_t qo = base + (size_t)(q0 + warp * 16) * kHeadDim + kk * 16;
        wmma::load_matrix_sync(fq[kk], g_q + qo, kHeadDim);
    }

    wmma::fragment<wmma::accumulator, 16, 16, 16, float> oacc[4];
#pragma unroll
    for (int nt4 = 0; nt4 < 4; nt4++) wmma::fill_fragment(oacc[nt4], 0.0f);

    const int rlow  = warp * 16 + (lane >> 2);
    const int qglow = q0 + rlow;
    float lacc0 = 0.f, lacc1 = 0.f;

    const int ntiles = 2 * qi + 2;
    loadKV(0, 0);

    for (int kt = 0; kt < ntiles; kt++) {
        const int k0  = kt * 64;
        const int buf = kt & 1;
        const bool needMask = (kt >= 2 * qi);   // only last two tiles touch the diagonal
        char* kv = sm + buf * kKVBuf;
        const __half* skh = (const __half*)(kv);
        const __half* svh = (const __half*)(kv + 9216);

        __pipeline_wait_prior(0);
        __syncthreads();
        if (kt + 1 < ntiles) loadKV(kt + 1, buf ^ 1);

        // S = Q K^T, softmax in registers, P -> smem single fp16
#pragma unroll
        for (int nt4 = 0; nt4 < 4; nt4++) {
            wmma::fragment<wmma::accumulator, 16, 16, 16, float> sacc;
            wmma::fill_fragment(sacc, 0.0f);
#pragma unroll
            for (int kk = 0; kk < 4; kk++) {
                wmma::fragment<wmma::matrix_b, 16, 16, 16, __half, wmma::col_major> fbh;
                wmma::load_matrix_sync(fbh, skh + (nt4 * 16) * 72 + kk * 16, 72);
                wmma::mma_sync(sacc, fq[kk], fbh, sacc);
            }
            if (needMask) {
#pragma unroll
                for (int i2 = 0; i2 < 4; i2++) {
                    const int i = 2 * i2;
                    const int rl   = rlow + ((i & 2) ? 8 : 0);
                    const int qg   = qglow + ((i & 2) ? 8 : 0);
                    const int colb = nt4 * 16 + (lane & 3) * 2 + ((i & 4) ? 8 : 0);
                    const int kg   = k0 + colb;
                    const float p0 = (kg     <= qg) ? exp2f(sacc.x[i])     : 0.f;
                    const float p1 = (kg + 1 <= qg) ? exp2f(sacc.x[i + 1]) : 0.f;
                    if (i & 2) lacc1 += p0 + p1; else lacc0 += p0 + p1;
                    __half2 hh; hh.x = __float2half(p0); hh.y = __float2half(p1);
                    *(__half2*)(ph + rl * 72 + colb) = hh;
                }
            } else {
#pragma unroll
                for (int i2 = 0; i2 < 4; i2++) {
                    const int i = 2 * i2;
                    const int rl   = rlow + ((i & 2) ? 8 : 0);
                    const int colb = nt4 * 16 + (lane & 3) * 2 + ((i & 4) ? 8 : 0);
                    const float p0 = exp2f(sacc.x[i]);
                    const float p1 = exp2f(sacc.x[i + 1]);
                    if (i & 2) lacc1 += p0 + p1; else lacc0 += p0 + p1;
                    __half2 hh; hh.x = __float2half(p0); hh.y = __float2half(p1);
                    *(__half2*)(ph + rl * 72 + colb) = hh;
                }
            }
        }
        __syncwarp();

        // O += P V
#pragma unroll
        for (int kk = 0; kk < 4; kk++) {
            wmma::fragment<wmma::matrix_a, 16, 16, 16, __half, wmma::row_major> fph;
            wmma::load_matrix_sync(fph, ph + (warp * 16) * 72 + kk * 16, 72);
#pragma unroll
            for (int nt4 = 0; nt4 < 4; nt4++) {
                wmma::fragment<wmma::matrix_b, 16, 16, 16, __half, wmma::row_major> fvh;
                wmma::load_matrix_sync(fvh, svh + (kk * 16) * 72 + nt4 * 16, 72);
                wmma::mma_sync(oacc[nt4], fph, fvh, oacc[nt4]);
            }
        }
    }

    lacc0 += __shfl_xor_sync(0xffffffffu, lacc0, 1);
    lacc0 += __shfl_xor_sync(0xffffffffu, lacc0, 2);
    lacc1 += __shfl_xor_sync(0xffffffffu, lacc1, 1);
    lacc1 += __shfl_xor_sync(0xffffffffu, lacc1, 2);
    const float inv0 = 1.f / lacc0;
    const float inv1 = 1.f / lacc1;

    const int b = bh >> 4, h = bh & 15;
#pragma unroll
    for (int nt4 = 0; nt4 < 4; nt4++) {
#pragma unroll
        for (int i2 = 0; i2 < 4; i2++) {
            const int i = 2 * i2;
            const int qg   = qglow + ((i & 2) ? 8 : 0);
            const float inv = (i & 2) ? inv1 : inv0;
            const int colb = nt4 * 16 + (lane & 3) * 2 + ((i & 4) ? 8 : 0);
            const float v0 = oacc[nt4].x[i]     * inv;
            const float v1 = oacc[nt4].x[i + 1] * inv;
            __half2 hh; hh.x = __float2half(v0); hh.y = __float2half(v1);
            const size_t o = ((size_t)(b * kSeq + qg)) * kEmbed + h * kHeadDim + colb;
            *(__half2*)(g_at + o) = hh;
        }
    }
}

// ======================= launch =======================
extern "C" void kernel_launch(void* const* d_in, const int* in_sizes, int n_in,
                              void* d_out, int out_size) {
    const float* x  = (const float*)d_in[0];
    const float* Wq = (const float*)d_in[1];
    const float* Wk = (const float*)d_in[2];
    const float* Wv = (const float*)d_in[3];
    const float* bq = (const float*)d_in[4];
    const float* bk = (const float*)d_in[5];
    const float* bv = (const float*)d_in[6];
    const float* Wp = (const float*)d_in[7];
    const float* bp = (const float*)d_in[8];
    float* out = (float*)d_out;

    cudaFuncSetAttribute(gemm_wmma_kernel, cudaFuncAttributeMaxDynamicSharedMemorySize, kGemmSmem);
    cudaFuncSetAttribute(attn_wmma_kernel, cudaFuncAttributeMaxDynamicSharedMemorySize, kAttnSmem);

    convert_x_kernel<<<(kRows * kEmbed + 255) / 256, 256>>>(x);
    pack_qkv_kernel<<<(kEmbed * kQkvN + 255) / 256, 256>>>(Wq, Wk, Wv, bq, bk, bv);
    pack_wp_kernel<<<(kEmbed * kEmbed + 255) / 256, 256>>>(Wp);

    // QKV projection: [8192,1024] x [1024,3072] -> fp16 q/k/v
    gemm_wmma_kernel<<<dim3(kQkvN / 128, kRows / 128), 128, kGemmSmem>>>(nullptr, nullptr, 0);

    // causal attention on tensor cores
    attn_wmma_kernel<<<dim3(kSeq / 128, kBatch * kHeads), 256, kAttnSmem>>>();

    // output projection: [8192,1024] x [1024,1024] + bias
    gemm_wmma_kernel<<<dim3(kEmbed / 128, kRows / 128), 128, kGemmSmem>>>(bp, out, 1);
}

// round 14
// speedup vs baseline: 4.5374x; 1.0553x over previous
#include <cuda_runtime.h>
#include <cuda_bf16.h>
#include <cuda_fp16.h>
#include <cuda_pipeline.h>
#include <mma.h>
#include <math.h>

using namespace nvcuda;

constexpr int kEmbed   = 1024;
constexpr int kHeads   = 16;
constexpr int kHeadDim = 64;
constexpr int kSeq     = 2048;
constexpr int kBatch   = 4;
constexpr int kQkvN    = 3 * kEmbed;          // 3072
constexpr int kRows    = kBatch * kSeq;       // 8192
constexpr int kBHT     = kBatch * kHeads * kSeq * kHeadDim;

// q pre-scale: 1/sqrt(64) * log2(e)  (softmax exp becomes exp2)
constexpr float kQScale = 0.125f * 1.4426950408889634f;

// -------- scratch (static device globals; no runtime allocation) --------
__device__ __align__(128) __half g_x[kRows * kEmbed];      // x single fp16
__device__ __align__(128) __half g_wqkv[kEmbed * kQkvN];   // weights single fp16
__device__ __align__(128) float g_bqkv[kQkvN];
// attention operands, all single fp16 (q pre-scaled by kQScale)
__device__ __align__(128) __half g_q[kBHT];
__device__ __align__(128) __half g_k[kBHT];
__device__ __align__(128) __half g_v[kBHT];
__device__ __align__(128) __half g_at[kRows * kEmbed];     // att single fp16
__device__ __align__(128) __half g_wp[kEmbed * kEmbed];    // single fp16

// ======================= conversion / packing =======================
__global__ void convert_x_kernel(const float* __restrict__ x) {
    int i = blockIdx.x * blockDim.x + threadIdx.x;
    if (i < kRows * kEmbed / 4) {
        float4 v = ((const float4*)x)[i];
        __half2 a = __floats2half2_rn(v.x, v.y);
        __half2 b = __floats2half2_rn(v.z, v.w);
        ((__half2*)g_x)[2 * i]     = a;
        ((__half2*)g_x)[2 * i + 1] = b;
    }
}

__global__ void pack_qkv_kernel(const float* __restrict__ Wq, const float* __restrict__ Wk,
                                const float* __restrict__ Wv, const float* __restrict__ bq,
                                const float* __restrict__ bk, const float* __restrict__ bv) {
    int idx = blockIdx.x * blockDim.x + threadIdx.x;
    if (idx < kEmbed * kQkvN) {
        int e = idx / kQkvN;
        int n = idx % kQkvN;
        int which = n >> 10;
        int hd    = n & 1023;
        int h = hd >> 6, d = hd & 63;
        const float* W = (which == 0) ? Wq : (which == 1) ? Wk : Wv;
        g_wqkv[idx] = __float2half(W[((size_t)h * kEmbed + e) * kHeadDim + d]);
    }
    if (idx < kQkvN) {
        int which = idx >> 10;
        int hd    = idx & 1023;
        const float* bb = (which == 0) ? bq : (which == 1) ? bk : bv;
        g_bqkv[idx] = bb[hd];
    }
}

__global__ void pack_wp_kernel(const float* __restrict__ Wp) {
    int i = blockIdx.x * blockDim.x + threadIdx.x;
    if (i < kEmbed * kEmbed / 4) {
        float4 v = ((const float4*)Wp)[i];
        __half2 a = __floats2half2_rn(v.x, v.y);
        __half2 b = __floats2half2_rn(v.z, v.w);
        ((__half2*)g_wp)[2 * i]     = a;
        ((__half2*)g_wp)[2 * i + 1] = b;
    }
}

// ======================= fp16 WMMA GEMM =======================
// acc += A*B (single fp16, fp32 accumulate). Block 128x128, BK=32,
// cp.async 3-stage, 128 threads / 4 warps (2m x 2n), warp tile 64x64, 2 CTAs/SM.
constexpr int kGA = 0;                       // [128][40] half = 10240
constexpr int kGB = 10240;                   // [32][136] half = 8704
constexpr int kGStage = 18944;
constexpr int kGemmSmem = 3 * kGStage;       // 56832

__global__ __launch_bounds__(128, 2)
void gemm_wmma_kernel(const float* __restrict__ bias_arg, float* __restrict__ outp, int mode) {
    extern __shared__ char sm[];

    const int N = (mode == 0) ? kQkvN : kEmbed;
    const __half* A = (mode == 0) ? g_x : g_at;
    const __half* B = (mode == 0) ? g_wqkv : g_wp;
    const float* bias = (mode == 0) ? g_bqkv : bias_arg;

    const int tid  = threadIdx.x;
    const int warp = tid >> 5, lane = tid & 31;
    const int wm   = warp >> 1, wn = warp & 1;   // 2 x 2 warp grid
    const int bm   = blockIdx.y * 128;
    const int bn   = blockIdx.x * 128;

    auto loadStage = [&](int kt, int s) {
        const int k0 = kt * 32;
        char* st = sm + s * kGStage;
        __half* sA = (__half*)(st + kGA);
        __half* sB = (__half*)(st + kGB);
#pragma unroll
        for (int i = 0; i < 4; i++) {
            const int idx = i * 128 + tid;
            const int ar = idx >> 2, ac = (idx & 3) * 8;
            const size_t asrc = (size_t)(bm + ar) * kEmbed + k0 + ac;
            __pipeline_memcpy_async(sA + ar * 40 + ac, A + asrc, 16);
            const int br = idx >> 4, bc = (idx & 15) * 8;
            const size_t bsrc = (size_t)(k0 + br) * N + bn + bc;
            __pipeline_memcpy_async(sB + br * 136 + bc, B + bsrc, 16);
        }
        __pipeline_commit();
    };

    wmma::fragment<wmma::accumulator, 16, 16, 16, float> acc[4][4];
#pragma unroll
    for (int mi = 0; mi < 4; mi++)
#pragma unroll
        for (int ni = 0; ni < 4; ni++) wmma::fill_fragment(acc[mi][ni], 0.0f);

    constexpr int NT = kEmbed / 32;
    loadStage(0, 0);
    loadStage(1, 1);

    for (int kt = 0; kt < NT; kt++) {
        if (kt < NT - 2) __pipeline_wait_prior(1);
        else             __pipeline_wait_prior(0);
        __syncthreads();
        if (kt + 2 < NT) loadStage(kt + 2, (kt + 2) % 3);

        char* st = sm + (kt % 3) * kGStage;
        const __half* sA = (const __half*)(st + kGA);
        const __half* sB = (const __half*)(st + kGB);

#pragma unroll
        for (int kk = 0; kk < 2; kk++) {
            wmma::fragment<wmma::matrix_a, 16, 16, 16, __half, wmma::row_major> fa[4];
            wmma::fragment<wmma::matrix_b, 16, 16, 16, __half, wmma::row_major> fb[4];
#pragma unroll
            for (int mi = 0; mi < 4; mi++)
                wmma::load_matrix_sync(fa[mi], sA + (wm * 64 + mi * 16) * 40 + kk * 16, 40);
#pragma unroll
            for (int ni = 0; ni < 4; ni++)
                wmma::load_matrix_sync(fb[ni], sB + (kk * 16) * 136 + wn * 64 + ni * 16, 136);
#pragma unroll
            for (int mi = 0; mi < 4; mi++)
#pragma unroll
                for (int ni = 0; ni < 4; ni++)
                    wmma::mma_sync(acc[mi][ni], fa[mi], fb[ni], acc[mi][ni]);
        }
    }

    // direct fragment epilogue (sm_80+ accumulator layout)
#pragma unroll
    for (int mi = 0; mi < 4; mi++) {
#pragma unroll
        for (int ni = 0; ni < 4; ni++) {
#pragma unroll
            for (int i2 = 0; i2 < 4; i2++) {
                const int i = 2 * i2;
                const int row = bm + wm * 64 + mi * 16 + (lane >> 2) + ((i & 2) ? 8 : 0);
                const int col = bn + wn * 64 + ni * 16 + (lane & 3) * 2 + ((i & 4) ? 8 : 0);
                float v0 = acc[mi][ni].x[i]     + bias[col];
                float v1 = acc[mi][ni].x[i + 1] + bias[col + 1];
                if (mode == 0) {
                    const int which = col >> 10, hd = col & 1023;
                    const int h = hd >> 6, d = hd & 63;
                    const int b = row >> 11, t = row & 2047;
                    const size_t o = (((size_t)(b * kHeads + h) * kSeq) + t) * kHeadDim + d;
                    if (which == 0) { v0 *= kQScale; v1 *= kQScale; }
                    __half* dst = (which == 0) ? g_q : ((which == 1) ? g_k : g_v);
                    *(__half2*)(dst + o) = __floats2half2_rn(v0, v1);
                } else {
                    float2 vv; vv.x = v0; vv.y = v1;
                    *(float2*)(outp + (size_t)row * kEmbed + col) = vv;
                }
            }
        }
    }
}

// ======================= fp16 WMMA causal attention =======================
// 256 threads, 128 q-rows/CTA, kv tile 64, cp.async double buffer.
// S = q*k (1 MMA), p = h2exp2(S) (scale folded into q, half2 MUFU), O += p*v.
constexpr int kKVBuf  = 2 * 9216;            // k, v each half[64][72]
constexpr int kAPH    = 2 * kKVBuf;          // 36864, half[128][72]
constexpr int kAttnSmem = kAPH + 18432;      // 55296

__global__ __launch_bounds__(256, 2)
void attn_wmma_kernel() {
    extern __shared__ char sm[];
    __half* ph = (__half*)(sm + kAPH);

    const int qi  = gridDim.x - 1 - blockIdx.x;   // big tiles first
    const int bh  = blockIdx.y;
    const int tid = threadIdx.x;
    const int warp = tid >> 5, lane = tid & 31;
    const int q0  = qi * 128;
    const size_t base = (size_t)bh * kSeq * kHeadDim;

    auto loadKV = [&](int kt, int b) {
        const int k0 = kt * 64;
        char* kv = sm + b * kKVBuf;
        __half* skh = (__half*)(kv);
        __half* svh = (__half*)(kv + 9216);
#pragma unroll
        for (int i = 0; i < 2; i++) {
            const int idx = i * 256 + tid;
            const int r = idx >> 3, c8 = (idx & 7) * 8;
            const size_t g = base + (size_t)(k0 + r) * kHeadDim + c8;
            const int so = r * 72 + c8;
            __pipeline_memcpy_async(skh + so, g_k + g, 16);
            __pipeline_memcpy_async(svh + so, g_v + g, 16);
        }
        __pipeline_commit();
    };

    wmma::fragment<wmma::matrix_a, 16, 16, 16, __half, wmma::row_major> fq[4];
#pragma unroll
    for (int kk = 0; kk < 4; kk++) {
        const size_t qo = base + (size_t)(q0 + warp * 16) * kHeadDim + kk * 16;
        wmma::load_matrix_sync(fq[kk], g_q + qo, kHeadDim);
    }

    wmma::fragment<wmma::accumulator, 16, 16, 16, float> oacc[4];
#pragma unroll
    for (int nt4 = 0; nt4 < 4; nt4++) wmma::fill_fragment(oacc[nt4], 0.0f);

    const int rlow  = warp * 16 + (lane >> 2);
    const int qglow = q0 + rlow;
    float lacc0 = 0.f, lacc1 = 0.f;

    const int ntiles = 2 * qi + 2;
    loadKV(0, 0);

    for (int kt = 0; kt < ntiles; kt++) {
        const int k0  = kt * 64;
        const int buf = kt & 1;
        const bool needMask = (kt >= 2 * qi);   // only last two tiles touch the diagonal
        char* kv = sm + buf * kKVBuf;
        const __half* skh = (const __half*)(kv);
        const __half* svh = (const __half*)(kv + 9216);

        __pipeline_wait_prior(0);
        __syncthreads();
        if (kt + 1 < ntiles) loadKV(kt + 1, buf ^ 1);

        // S = Q K^T, half2 softmax in registers, P -> smem fp16
#pragma unroll
        for (int nt4 = 0; nt4 < 4; nt4++) {
            wmma::fragment<wmma::accumulator, 16, 16, 16, float> sacc;
            wmma::fill_fragment(sacc, 0.0f);
#pragma unroll
            for (int kk = 0; kk < 4; kk++) {
                wmma::fragment<wmma::matrix_b, 16, 16, 16, __half, wmma::col_major> fbh;
                wmma::load_matrix_sync(fbh, skh + (nt4 * 16) * 72 + kk * 16, 72);
                wmma::mma_sync(sacc, fq[kk], fbh, sacc);
            }
#pragma unroll
            for (int i2 = 0; i2 < 4; i2++) {
                const int i = 2 * i2;
                const int rl   = rlow + ((i & 2) ? 8 : 0);
                const int colb = nt4 * 16 + (lane & 3) * 2 + ((i & 4) ? 8 : 0);
                float s0 = sacc.x[i], s1 = sacc.x[i + 1];
                if (needMask) {
                    const int qg = qglow + ((i & 2) ? 8 : 0);
                    const int kg = k0 + colb;
                    if (kg     > qg) s0 = -INFINITY;
                    if (kg + 1 > qg) s1 = -INFINITY;
                }
                const __half2 hp = h2exp2(__floats2half2_rn(s0, s1));
                *(__half2*)(ph + rl * 72 + colb) = hp;
                const float2 lf = __half22float2(hp);   // sum the exact MMA inputs
                if (i & 2) lacc1 += lf.x + lf.y; else lacc0 += lf.x + lf.y;
            }
        }
        __syncwarp();

        // O += P V
#pragma unroll
        for (int kk = 0; kk < 4; kk++) {
            wmma::fragment<wmma::matrix_a, 16, 16, 16, __half, wmma::row_major> fph;
            wmma::load_matrix_sync(fph, ph + (warp * 16) * 72 + kk * 16, 72);
#pragma unroll
            for (int nt4 = 0; nt4 < 4; nt4++) {
                wmma::fragment<wmma::matrix_b, 16, 16, 16, __half, wmma::row_major> fvh;
                wmma::load_matrix_sync(fvh, svh + (kk * 16) * 72 + nt4 * 16, 72);
                wmma::mma_sync(oacc[nt4], fph, fvh, oacc[nt4]);
            }
        }
    }

    lacc0 += __shfl_xor_sync(0xffffffffu, lacc0, 1);
    lacc0 += __shfl_xor_sync(0xffffffffu, lacc0, 2);
    lacc1 += __shfl_xor_sync(0xffffffffu, lacc1, 1);
    lacc1 += __shfl_xor_sync(0xffffffffu, lacc1, 2);
    const float inv0 = 1.f / lacc0;
    const float inv1 = 1.f / lacc1;

    const int b = bh >> 4, h = bh & 15;
#pragma unroll
    for (int nt4 = 0; nt4 < 4; nt4++) {
#pragma unroll
        for (int i2 = 0; i2 < 4; i2++) {
            const int i = 2 * i2;
            const int qg   = qglow + ((i & 2) ? 8 : 0);
            const float inv = (i & 2) ? inv1 : inv0;
            const int colb = nt4 * 16 + (lane & 3) * 2 + ((i & 4) ? 8 : 0);
            const float v0 = oacc[nt4].x[i]     * inv;
            const float v1 = oacc[nt4].x[i + 1] * inv;
            const size_t o = ((size_t)(b * kSeq + qg)) * kEmbed + h * kHeadDim + colb;
            *(__half2*)(g_at + o) = __floats2half2_rn(v0, v1);
        }
    }
}

// ======================= launch =======================
extern "C" void kernel_launch(void* const* d_in, const int* in_sizes, int n_in,
                              void* d_out, int out_size) {
    const float* x  = (const float*)d_in[0];
    const float* Wq = (const float*)d_in[1];
    const float* Wk = (const float*)d_in[2];
    const float* Wv = (const float*)d_in[3];
    const float* bq = (const float*)d_in[4];
    const float* bk = (const float*)d_in[5];
    const float* bv = (const float*)d_in[6];
    const float* Wp = (const float*)d_in[7];
    const float* bp = (const float*)d_in[8];
    float* out = (float*)d_out;

    cudaFuncSetAttribute(gemm_wmma_kernel, cudaFuncAttributeMaxDynamicSharedMemorySize, kGemmSmem);
    cudaFuncSetAttribute(attn_wmma_kernel, cudaFuncAttributeMaxDynamicSharedMemorySize, kAttnSmem);

    convert_x_kernel<<<(kRows * kEmbed / 4 + 255) / 256, 256>>>(x);
    pack_qkv_kernel<<<(kEmbed * kQkvN + 255) / 256, 256>>>(Wq, Wk, Wv, bq, bk, bv);
    pack_wp_kernel<<<(kEmbed * kEmbed / 4 + 255) / 256, 256>>>(Wp);

    // QKV projection: [8192,1024] x [1024,3072] -> fp16 q/k/v
    gemm_wmma_kernel<<<dim3(kQkvN / 128, kRows / 128), 128, kGemmSmem>>>(nullptr, nullptr, 0);

    // causal attention on tensor cores
    attn_wmma_kernel<<<dim3(kSeq / 128, kBatch * kHeads), 256, kAttnSmem>>>();

    // output projection: [8192,1024] x [1024,1024] + bias
    gemm_wmma_kernel<<<dim3(kEmbed / 128, kRows / 128), 128, kGemmSmem>>>(bp, out, 1);
}

// round 15
// speedup vs baseline: 4.6820x; 1.0319x over previous
#include <cuda_runtime.h>
#include <cuda_bf16.h>
#include <cuda_fp16.h>
#include <cuda_pipeline.h>
#include <mma.h>
#include <math.h>

using namespace nvcuda;

constexpr int kEmbed   = 1024;
constexpr int kHeads   = 16;
constexpr int kHeadDim = 64;
constexpr int kSeq     = 2048;
constexpr int kBatch   = 4;
constexpr int kQkvN    = 3 * kEmbed;          // 3072
constexpr int kRows    = kBatch * kSeq;       // 8192
constexpr int kBHT     = kBatch * kHeads * kSeq * kHeadDim;

// q pre-scale: 1/sqrt(64) * log2(e)  (softmax exp becomes exp2)
constexpr float kQScale = 0.125f * 1.4426950408889634f;

// -------- scratch (static device globals; no runtime allocation) --------
__device__ __align__(128) __half g_x[kRows * kEmbed];      // x single fp16
__device__ __align__(128) __half g_wqkv[kEmbed * kQkvN];   // weights single fp16
__device__ __align__(128) float g_bqkv[kQkvN];
// attention operands, all single fp16 (q pre-scaled by kQScale)
__device__ __align__(128) __half g_q[kBHT];
__device__ __align__(128) __half g_k[kBHT];
__device__ __align__(128) __half g_v[kBHT];
__device__ __align__(128) __half g_at[kRows * kEmbed];     // att single fp16
__device__ __align__(128) __half g_wp[kEmbed * kEmbed];    // single fp16

// ======================= fused conversion / packing =======================
// range 1: x -> fp16 (float4 granular), range 2: Wp -> fp16 (float4),
// range 3: Wq/Wk/Wv gather-pack (elementwise) + bias pack.
constexpr int kCvt1 = kRows * kEmbed / 4;          // 2097152
constexpr int kCvt2 = kCvt1 + kEmbed * kEmbed / 4; // +262144
constexpr int kCvt3 = kCvt2 + kEmbed * kQkvN;      // +3145728

__global__ void pack_all_kernel(const float* __restrict__ x, const float* __restrict__ Wp,
                                const float* __restrict__ Wq, const float* __restrict__ Wk,
                                const float* __restrict__ Wv, const float* __restrict__ bq,
                                const float* __restrict__ bk, const float* __restrict__ bv) {
    int idx = blockIdx.x * blockDim.x + threadIdx.x;
    if (idx < kCvt1) {
        float4 v = ((const float4*)x)[idx];
        ((__half2*)g_x)[2 * idx]     = __floats2half2_rn(v.x, v.y);
        ((__half2*)g_x)[2 * idx + 1] = __floats2half2_rn(v.z, v.w);
    } else if (idx < kCvt2) {
        const int i = idx - kCvt1;
        float4 v = ((const float4*)Wp)[i];
        ((__half2*)g_wp)[2 * i]     = __floats2half2_rn(v.x, v.y);
        ((__half2*)g_wp)[2 * i + 1] = __floats2half2_rn(v.z, v.w);
    } else if (idx < kCvt3) {
        const int i = idx - kCvt2;
        const int e = i / kQkvN;
        const int n = i % kQkvN;
        const int which = n >> 10;
        const int hd    = n & 1023;
        const int h = hd >> 6, d = hd & 63;
        const float* W = (which == 0) ? Wq : (which == 1) ? Wk : Wv;
        g_wqkv[i] = __float2half(W[((size_t)h * kEmbed + e) * kHeadDim + d]);
        if (i < kQkvN) {
            const int wh = i >> 10, bhd = i & 1023;
            const float* bb = (wh == 0) ? bq : (wh == 1) ? bk : bv;
            g_bqkv[i] = bb[bhd];
        }
    }
}

// ======================= fp16 WMMA GEMM =======================
// acc += A*B (single fp16, fp32 accumulate). Block 128x128, BK=32,
// cp.async 3-stage, 128 threads / 4 warps (2m x 2n), warp tile 64x64, 2 CTAs/SM.
constexpr int kGA = 0;                       // [128][40] half = 10240
constexpr int kGB = 10240;                   // [32][136] half = 8704
constexpr int kGStage = 18944;
constexpr int kGemmSmem = 3 * kGStage;       // 56832

__global__ __launch_bounds__(128, 2)
void gemm_wmma_kernel(const float* __restrict__ bias_arg, float* __restrict__ outp, int mode) {
    extern __shared__ char sm[];

    const int N = (mode == 0) ? kQkvN : kEmbed;
    const __half* A = (mode == 0) ? g_x : g_at;
    const __half* B = (mode == 0) ? g_wqkv : g_wp;
    const float* bias = (mode == 0) ? g_bqkv : bias_arg;

    const int tid  = threadIdx.x;
    const int warp = tid >> 5, lane = tid & 31;
    const int wm   = warp >> 1, wn = warp & 1;   // 2 x 2 warp grid
    const int bm   = blockIdx.y * 128;
    const int bn   = blockIdx.x * 128;

    auto loadStage = [&](int kt, int s) {
        const int k0 = kt * 32;
        char* st = sm + s * kGStage;
        __half* sA = (__half*)(st + kGA);
        __half* sB = (__half*)(st + kGB);
#pragma unroll
        for (int i = 0; i < 4; i++) {
            const int idx = i * 128 + tid;
            const int ar = idx >> 2, ac = (idx & 3) * 8;
            const size_t asrc = (size_t)(bm + ar) * kEmbed + k0 + ac;
            __pipeline_memcpy_async(sA + ar * 40 + ac, A + asrc, 16);
            const int br = idx >> 4, bc = (idx & 15) * 8;
            const size_t bsrc = (size_t)(k0 + br) * N + bn + bc;
            __pipeline_memcpy_async(sB + br * 136 + bc, B + bsrc, 16);
        }
        __pipeline_commit();
    };

    wmma::fragment<wmma::accumulator, 16, 16, 16, float> acc[4][4];
#pragma unroll
    for (int mi = 0; mi < 4; mi++)
#pragma unroll
        for (int ni = 0; ni < 4; ni++) wmma::fill_fragment(acc[mi][ni], 0.0f);

    constexpr int NT = kEmbed / 32;
    loadStage(0, 0);
    loadStage(1, 1);

    for (int kt = 0; kt < NT; kt++) {
        if (kt < NT - 2) __pipeline_wait_prior(1);
        else             __pipeline_wait_prior(0);
        __syncthreads();
        if (kt + 2 < NT) loadStage(kt + 2, (kt + 2) % 3);

        char* st = sm + (kt % 3) * kGStage;
        const __half* sA = (const __half*)(st + kGA);
        const __half* sB = (const __half*)(st + kGB);

#pragma unroll
        for (int kk = 0; kk < 2; kk++) {
            wmma::fragment<wmma::matrix_a, 16, 16, 16, __half, wmma::row_major> fa[4];
            wmma::fragment<wmma::matrix_b, 16, 16, 16, __half, wmma::row_major> fb[4];
#pragma unroll
            for (int mi = 0; mi < 4; mi++)
                wmma::load_matrix_sync(fa[mi], sA + (wm * 64 + mi * 16) * 40 + kk * 16, 40);
#pragma unroll
            for (int ni = 0; ni < 4; ni++)
                wmma::load_matrix_sync(fb[ni], sB + (kk * 16) * 136 + wn * 64 + ni * 16, 136);
#pragma unroll
            for (int mi = 0; mi < 4; mi++)
#pragma unroll
                for (int ni = 0; ni < 4; ni++)
                    wmma::mma_sync(acc[mi][ni], fa[mi], fb[ni], acc[mi][ni]);
        }
    }

    // direct fragment epilogue (sm_80+ accumulator layout)
#pragma unroll
    for (int mi = 0; mi < 4; mi++) {
#pragma unroll
        for (int ni = 0; ni < 4; ni++) {
#pragma unroll
            for (int i2 = 0; i2 < 4; i2++) {
                const int i = 2 * i2;
                const int row = bm + wm * 64 + mi * 16 + (lane >> 2) + ((i & 2) ? 8 : 0);
                const int col = bn + wn * 64 + ni * 16 + (lane & 3) * 2 + ((i & 4) ? 8 : 0);
                float v0 = acc[mi][ni].x[i]     + bias[col];
                float v1 = acc[mi][ni].x[i + 1] + bias[col + 1];
                if (mode == 0) {
                    const int which = col >> 10, hd = col & 1023;
                    const int h = hd >> 6, d = hd & 63;
                    const int b = row >> 11, t = row & 2047;
                    const size_t o = (((size_t)(b * kHeads + h) * kSeq) + t) * kHeadDim + d;
                    if (which == 0) { v0 *= kQScale; v1 *= kQScale; }
                    __half* dst = (which == 0) ? g_q : ((which == 1) ? g_k : g_v);
                    *(__half2*)(dst + o) = __floats2half2_rn(v0, v1);
                } else {
                    float2 vv; vv.x = v0; vv.y = v1;
                    *(float2*)(outp + (size_t)row * kEmbed + col) = vv;
                }
            }
        }
    }
}

// ======================= fp16 WMMA causal attention =======================
// 256 threads, 128 q-rows/CTA, kv tile 64, cp.async double buffer.
// S = q*k (1 MMA), p = h2exp2(S) converted IN-REGISTER to a matrix_a fragment
// (acc and A fragments share the ldmatrix thread mapping), O += p*v.
constexpr int kKVBuf  = 2 * 9216;            // k, v each half[64][72]
constexpr int kAttnSmem = 2 * kKVBuf;        // 36864

__global__ __launch_bounds__(256, 2)
void attn_wmma_kernel() {
    extern __shared__ char sm[];

    const int qi  = gridDim.x - 1 - blockIdx.x;   // big tiles first
    const int bh  = blockIdx.y;
    const int tid = threadIdx.x;
    const int warp = tid >> 5, lane = tid & 31;
    const int q0  = qi * 128;
    const size_t base = (size_t)bh * kSeq * kHeadDim;

    auto loadKV = [&](int kt, int b) {
        const int k0 = kt * 64;
        char* kv = sm + b * kKVBuf;
        __half* skh = (__half*)(kv);
        __half* svh = (__half*)(kv + 9216);
#pragma unroll
        for (int i = 0; i < 2; i++) {
            const int idx = i * 256 + tid;
            const int r = idx >> 3, c8 = (idx & 7) * 8;
            const size_t g = base + (size_t)(k0 + r) * kHeadDim + c8;
            const int so = r * 72 + c8;
            __pipeline_memcpy_async(skh + so, g_k + g, 16);
            __pipeline_memcpy_async(svh + so, g_v + g, 16);
        }
        __pipeline_commit();
    };

    wmma::fragment<wmma::matrix_a, 16, 16, 16, __half, wmma::row_major> fq[4];
#pragma unroll
    for (int kk = 0; kk < 4; kk++) {
        const size_t qo = base + (size_t)(q0 + warp * 16) * kHeadDim + kk * 16;
        wmma::load_matrix_sync(fq[kk], g_q + qo, kHeadDim);
    }

    wmma::fragment<wmma::accumulator, 16, 16, 16, float> oacc[4];
#pragma unroll
    for (int d4 = 0; d4 < 4; d4++) wmma::fill_fragment(oacc[d4], 0.0f);

    const int rlow  = warp * 16 + (lane >> 2);
    const int qglow = q0 + rlow;
    float lacc0 = 0.f, lacc1 = 0.f;

    const int ntiles = 2 * qi + 2;
    loadKV(0, 0);

    for (int kt = 0; kt < ntiles; kt++) {
        const int k0  = kt * 64;
        const int buf = kt & 1;
        const bool needMask = (kt >= 2 * qi);   // only last two tiles touch the diagonal
        char* kv = sm + buf * kKVBuf;
        const __half* skh = (const __half*)(kv);
        const __half* svh = (const __half*)(kv + 9216);

        __pipeline_wait_prior(0);
        __syncthreads();
        if (kt + 1 < ntiles) loadKV(kt + 1, buf ^ 1);

        // per 16-col block: S = Q K^T, softmax in registers -> matrix_a frag, O += P V
#pragma unroll
        for (int nt4 = 0; nt4 < 4; nt4++) {
            wmma::fragment<wmma::accumulator, 16, 16, 16, float> sacc;
            wmma::fill_fragment(sacc, 0.0f);
#pragma unroll
            for (int kk = 0; kk < 4; kk++) {
                wmma::fragment<wmma::matrix_b, 16, 16, 16, __half, wmma::col_major> fbh;
                wmma::load_matrix_sync(fbh, skh + (nt4 * 16) * 72 + kk * 16, 72);
                wmma::mma_sync(sacc, fq[kk], fbh, sacc);
            }

            wmma::fragment<wmma::matrix_a, 16, 16, 16, __half, wmma::row_major> fp;
#pragma unroll
            for (int i2 = 0; i2 < 4; i2++) {
                const int i = 2 * i2;
                float s0 = sacc.x[i], s1 = sacc.x[i + 1];
                if (needMask) {
                    const int qg = qglow + ((i & 2) ? 8 : 0);
                    const int kg = k0 + nt4 * 16 + (lane & 3) * 2 + ((i & 4) ? 8 : 0);
                    if (kg     > qg) s0 = -INFINITY;
                    if (kg + 1 > qg) s1 = -INFINITY;
                }
                const __half2 hp = h2exp2(__floats2half2_rn(s0, s1));
                fp.x[i]     = __low2half(hp);
                fp.x[i + 1] = __high2half(hp);
                const float2 lf = __half22float2(hp);
                if (i & 2) lacc1 += lf.x + lf.y; else lacc0 += lf.x + lf.y;
            }

#pragma unroll
            for (int d4 = 0; d4 < 4; d4++) {
                wmma::fragment<wmma::matrix_b, 16, 16, 16, __half, wmma::row_major> fvh;
                wmma::load_matrix_sync(fvh, svh + (nt4 * 16) * 72 + d4 * 16, 72);
                wmma::mma_sync(oacc[d4], fp, fvh, oacc[d4]);
            }
        }
    }

    lacc0 += __shfl_xor_sync(0xffffffffu, lacc0, 1);
    lacc0 += __shfl_xor_sync(0xffffffffu, lacc0, 2);
    lacc1 += __shfl_xor_sync(0xffffffffu, lacc1, 1);
    lacc1 += __shfl_xor_sync(0xffffffffu, lacc1, 2);
    const float inv0 = 1.f / lacc0;
    const float inv1 = 1.f / lacc1;

    const int b = bh >> 4, h = bh & 15;
#pragma unroll
    for (int d4 = 0; d4 < 4; d4++) {
#pragma unroll
        for (int i2 = 0; i2 < 4; i2++) {
            const int i = 2 * i2;
            const int qg   = qglow + ((i & 2) ? 8 : 0);
            const float inv = (i & 2) ? inv1 : inv0;
            const int colb = d4 * 16 + (lane & 3) * 2 + ((i & 4) ? 8 : 0);
            const float v0 = oacc[d4].x[i]     * inv;
            const float v1 = oacc[d4].x[i + 1] * inv;
            const size_t o = ((size_t)(b * kSeq + qg)) * kEmbed + h * kHeadDim + colb;
            *(__half2*)(g_at + o) = __floats2half2_rn(v0, v1);
        }
    }
}

// ======================= launch =======================
extern "C" void kernel_launch(void* const* d_in, const int* in_sizes, int n_in,
                              void* d_out, int out_size) {
    const float* x  = (const float*)d_in[0];
    const float* Wq = (const float*)d_in[1];
    const float* Wk = (const float*)d_in[2];
    const float* Wv = (const float*)d_in[3];
    const float* bq = (const float*)d_in[4];
    const float* bk = (const float*)d_in[5];
    const float* bv = (const float*)d_in[6];
    const float* Wp = (const float*)d_in[7];
    const float* bp = (const float*)d_in[8];
    float* out = (float*)d_out;

    cudaFuncSetAttribute(gemm_wmma_kernel, cudaFuncAttributeMaxDynamicSharedMemorySize, kGemmSmem);
    cudaFuncSetAttribute(attn_wmma_kernel, cudaFuncAttributeMaxDynamicSharedMemorySize, kAttnSmem);

    // fused input/weight conversion + packing
    pack_all_kernel<<<(kCvt3 + 255) / 256, 256>>>(x, Wp, Wq, Wk, Wv, bq, bk, bv);

    // QKV projection: [8192,1024] x [1024,3072] -> fp16 q/k/v
    gemm_wmma_kernel<<<dim3(kQkvN / 128, kRows / 128), 128, kGemmSmem>>>(nullptr, nullptr, 0);

    // causal attention on tensor cores
    attn_wmma_kernel<<<dim3(kSeq / 128, kBatch * kHeads), 256, kAttnSmem>>>();

    // output projection: [8192,1024] x [1024,1024] + bias
    gemm_wmma_kernel<<<dim3(kEmbed / 128, kRows / 128), 128, kGemmSmem>>>(bp, out, 1);
}